// round 1
// baseline (speedup 1.0000x reference)
#include <cuda_runtime.h>
#include <math.h>

#define B_  2
#define T_  2048
#define C_  1024
#define H_  16
#define HS_ 64
#define NB_ 32
#define BLK_ 64
#define NSEL_ 8
#define WSZ_ 128

// ---------------- device scratch (allocation-free rule: __device__ globals) ----------------
__device__ float g_q[B_*T_*C_];
__device__ float g_k[B_*T_*C_];
__device__ float g_v[B_*T_*C_];
__device__ float g_attn[B_*T_*C_];
__device__ float g_gates[B_*T_*3];
__device__ float g_krep[B_*H_*NB_*HS_];
__device__ float g_vcmp[B_*H_*NB_*HS_];
__device__ float g_qbar[B_*H_*HS_];
__device__ int   g_topidx[B_*H_*NSEL_];
__device__ float g_selk[B_*H_*NSEL_*BLK_*HS_];
__device__ float g_selv[B_*H_*NSEL_*BLK_*HS_];

// ---------------- 128x128x8 SGEMM with bias: C = A[MxK] @ B[KxN] + bias ----------------
__global__ void __launch_bounds__(256) sgemm_bias_kernel(
    const float* __restrict__ A, const float* __restrict__ Bm,
    const float* __restrict__ bias, float* __restrict__ Cm,
    int M, int N, int K)
{
    __shared__ float As[8][128];
    __shared__ float Bs[8][128];
    int tid = threadIdx.x;
    int bx = blockIdx.x, by = blockIdx.y;
    int ar = tid >> 1, ac = (tid & 1) << 2;
    int br = tid >> 5, bc = (tid & 31) << 2;
    int ty = tid >> 4, tx = tid & 15;
    const float* Ab = A + (size_t)(by * 128) * K;
    const float* Bb = Bm + bx * 128;
    float acc[8][8];
#pragma unroll
    for (int i = 0; i < 8; i++)
#pragma unroll
        for (int j = 0; j < 8; j++) acc[i][j] = 0.f;

    for (int k0 = 0; k0 < K; k0 += 8) {
        float4 av = *(const float4*)(Ab + (size_t)ar * K + k0 + ac);
        As[ac + 0][ar] = av.x; As[ac + 1][ar] = av.y;
        As[ac + 2][ar] = av.z; As[ac + 3][ar] = av.w;
        *(float4*)&Bs[br][bc] = *(const float4*)(Bb + (size_t)(k0 + br) * N + bc);
        __syncthreads();
#pragma unroll
        for (int kk = 0; kk < 8; kk++) {
            float a[8], bb[8];
            *(float4*)&a[0]  = *(float4*)&As[kk][ty * 8];
            *(float4*)&a[4]  = *(float4*)&As[kk][ty * 8 + 4];
            *(float4*)&bb[0] = *(float4*)&Bs[kk][tx * 8];
            *(float4*)&bb[4] = *(float4*)&Bs[kk][tx * 8 + 4];
#pragma unroll
            for (int i = 0; i < 8; i++)
#pragma unroll
                for (int j = 0; j < 8; j++) acc[i][j] += a[i] * bb[j];
        }
        __syncthreads();
    }
#pragma unroll
    for (int i = 0; i < 8; i++) {
        int row = by * 128 + ty * 8 + i;
        float* cp = Cm + (size_t)row * N + bx * 128 + tx * 8;
        const float* bp = bias + bx * 128 + tx * 8;
#pragma unroll
        for (int j = 0; j < 8; j++) cp[j] = acc[i][j] + bp[j];
    }
}

// ---------------- gates = softmax(x @ Wg + bg), one warp per token ----------------
__global__ void gates_kernel(const float* __restrict__ x,
                             const float* __restrict__ Wg,
                             const float* __restrict__ bg)
{
    int gidx = blockIdx.x * blockDim.x + threadIdx.x;
    int w = gidx >> 5, lane = gidx & 31;
    if (w >= B_ * T_) return;
    const float* xr = x + (size_t)w * C_;
    float s0 = 0, s1 = 0, s2 = 0;
    for (int c = lane; c < C_; c += 32) {
        float xv = xr[c];
        s0 += xv * Wg[c * 3 + 0];
        s1 += xv * Wg[c * 3 + 1];
        s2 += xv * Wg[c * 3 + 2];
    }
#pragma unroll
    for (int o = 16; o; o >>= 1) {
        s0 += __shfl_xor_sync(0xffffffffu, s0, o);
        s1 += __shfl_xor_sync(0xffffffffu, s1, o);
        s2 += __shfl_xor_sync(0xffffffffu, s2, o);
    }
    if (lane == 0) {
        s0 += bg[0]; s1 += bg[1]; s2 += bg[2];
        float mx = fmaxf(s0, fmaxf(s1, s2));
        float e0 = __expf(s0 - mx), e1 = __expf(s1 - mx), e2 = __expf(s2 - mx);
        float inv = 1.f / (e0 + e1 + e2);
        g_gates[w * 3 + 0] = e0 * inv;
        g_gates[w * 3 + 1] = e1 * inv;
        g_gates[w * 3 + 2] = e2 * inv;
    }
}

// ---------------- per-block mean of K and V: k_rep, v_cmp ----------------
__global__ void blockmean_kernel()
{
    int idx = blockIdx.x * blockDim.x + threadIdx.x;
    if (idx >= B_ * H_ * NB_ * HS_) return;
    int d = idx & 63;
    int n = (idx >> 6) & 31;
    int h = (idx >> 11) & 15;
    int b = idx >> 15;
    const float* kp = g_k + ((size_t)(b * T_ + n * BLK_)) * C_ + h * HS_ + d;
    const float* vp = g_v + ((size_t)(b * T_ + n * BLK_)) * C_ + h * HS_ + d;
    float sk = 0.f, sv = 0.f;
    for (int j = 0; j < BLK_; j++) {
        sk += kp[(size_t)j * C_];
        sv += vp[(size_t)j * C_];
    }
    g_krep[idx] = sk * (1.f / BLK_);
    g_vcmp[idx] = sv * (1.f / BLK_);
}

// ---------------- qbar[b,h,:] = sum_t q_t / max(||q_t||, eps)  (mean factor dropped: topk-invariant) ----------------
__global__ void qbar_kernel()
{
    int b = blockIdx.x >> 4, h = blockIdx.x & 15;
    int warp = threadIdx.x >> 5, lane = threadIdx.x & 31;
    float a0 = 0.f, a1 = 0.f;
    for (int t = warp; t < T_; t += 8) {
        const float* qr = g_q + ((size_t)(b * T_ + t)) * C_ + h * HS_;
        float x0 = qr[lane], x1 = qr[lane + 32];
        float ss = x0 * x0 + x1 * x1;
#pragma unroll
        for (int o = 16; o; o >>= 1) ss += __shfl_xor_sync(0xffffffffu, ss, o);
        float inv = 1.f / fmaxf(sqrtf(ss), 1e-8f);
        a0 += x0 * inv;
        a1 += x1 * inv;
    }
    __shared__ float acc[64];
    if (threadIdx.x < 64) acc[threadIdx.x] = 0.f;
    __syncthreads();
    atomicAdd(&acc[lane], a0);
    atomicAdd(&acc[lane + 32], a1);
    __syncthreads();
    if (threadIdx.x < 64) g_qbar[blockIdx.x * 64 + threadIdx.x] = acc[threadIdx.x];
}

// ---------------- cosine scores + descending top-8 (stable: lowest index wins ties) ----------------
__global__ void topk_kernel()
{
    int bh = blockIdx.x;
    int n = threadIdx.x;  // 32 threads
    const float* kr = g_krep + ((size_t)bh * NB_ + n) * HS_;
    const float* qb = g_qbar + (size_t)bh * HS_;
    float dot = 0.f, ss = 0.f;
    for (int d = 0; d < HS_; d++) {
        float kv = kr[d];
        dot += kv * qb[d];
        ss += kv * kv;
    }
    float score = dot / fmaxf(sqrtf(ss), 1e-8f);
    __shared__ float sc[NB_];
    sc[n] = score;
    __syncthreads();
    if (n == 0) {
        bool used[NB_];
        for (int m = 0; m < NB_; m++) used[m] = false;
        for (int s = 0; s < NSEL_; s++) {
            float best = -1e30f; int bi = 0;
            for (int m = 0; m < NB_; m++)
                if (!used[m] && sc[m] > best) { best = sc[m]; bi = m; }
            used[bi] = true;
            g_topidx[bh * NSEL_ + s] = bi;
        }
    }
}

// ---------------- gather selected K/V blocks in top-k order ----------------
__global__ void gather_kernel()
{
    int idx = blockIdx.x * blockDim.x + threadIdx.x;
    if (idx >= B_ * H_ * NSEL_ * BLK_ * HS_) return;
    int d = idx & 63;
    int s = (idx >> 6) & 511;
    int h = (idx >> 15) & 15;
    int b = idx >> 19;
    int blk = g_topidx[(b * H_ + h) * NSEL_ + (s >> 6)];
    int row = blk * BLK_ + (s & 63);
    size_t src = ((size_t)(b * T_ + row)) * C_ + h * HS_ + d;
    g_selk[idx] = g_k[src];
    g_selv[idx] = g_v[src];
}

// ---------------- attention: 1 thread = 1 query, K/V tiles in smem, online softmax ----------------
// MODE 0: sliding window (j<=i, i-j<=128), K/V from g_k/g_v [B,T,C]
// MODE 1: selected (concat-pos js<=i),    K/V from g_selk/g_selv [B,H,512,64]
// MODE 2: compressed (block n<=i),        K/V from g_krep/g_vcmp [B,H,32,64]
template <int MODE>
__global__ void __launch_bounds__(128) attn_kernel()
{
    int q0 = blockIdx.x * 128;
    int h = blockIdx.y, b = blockIdx.z;
    int i = q0 + threadIdx.x;

    float qv[64];
    const float* qr = g_q + ((size_t)(b * T_ + i)) * C_ + h * HS_;
#pragma unroll
    for (int c = 0; c < 16; c++) *(float4*)&qv[c * 4] = *(const float4*)(qr + c * 4);

    __shared__ float4 Ks[64 * 16];
    __shared__ float4 Vs[64 * 16];

    float m = -1e30f, l = 0.f;
    float acc[64];
#pragma unroll
    for (int d = 0; d < 64; d++) acc[d] = 0.f;
    const float scale = 0.125f;  // 1/sqrt(64)

    int kt0, kt1, nrows;
    if (MODE == 0) { kt0 = (q0 > WSZ_ ? (q0 - WSZ_) >> 6 : 0); kt1 = (q0 + 127) >> 6; nrows = 64; }
    else if (MODE == 1) { kt0 = 0; int m1 = (q0 + 127) >> 6; kt1 = (m1 < 7 ? m1 : 7); nrows = 64; }
    else { kt0 = 0; kt1 = 0; nrows = 32; }

    for (int kt = kt0; kt <= kt1; kt++) {
        const float* ksrc; const float* vsrc; int kstride;
        if (MODE == 0) {
            ksrc = g_k + ((size_t)(b * T_ + kt * 64)) * C_ + h * HS_;
            vsrc = g_v + ((size_t)(b * T_ + kt * 64)) * C_ + h * HS_;
            kstride = C_;
        } else if (MODE == 1) {
            ksrc = g_selk + ((size_t)((b * H_ + h) * 512 + kt * 64)) * HS_;
            vsrc = g_selv + ((size_t)((b * H_ + h) * 512 + kt * 64)) * HS_;
            kstride = HS_;
        } else {
            ksrc = g_krep + ((size_t)(b * H_ + h) * NB_) * HS_;
            vsrc = g_vcmp + ((size_t)(b * H_ + h) * NB_) * HS_;
            kstride = HS_;
        }
        for (int idx = threadIdx.x; idx < nrows * 16; idx += 128) {
            int r = idx >> 4, c = idx & 15;
            Ks[idx] = *(const float4*)(ksrc + (size_t)r * kstride + c * 4);
            Vs[idx] = *(const float4*)(vsrc + (size_t)r * kstride + c * 4);
        }
        __syncthreads();

        for (int j = 0; j < nrows; j++) {
            int jj = kt * 64 + j;
            bool valid = (jj <= i);
            if (MODE == 0) valid = valid && (i - jj <= WSZ_);
            if (valid) {
                float s = 0.f;
#pragma unroll
                for (int c = 0; c < 16; c++) {
                    float4 kk = Ks[j * 16 + c];
                    s += qv[c * 4] * kk.x + qv[c * 4 + 1] * kk.y
                       + qv[c * 4 + 2] * kk.z + qv[c * 4 + 3] * kk.w;
                }
                s *= scale;
                if (s > m) {
                    float corr = __expf(m - s);
                    l *= corr;
#pragma unroll
                    for (int d = 0; d < 64; d++) acc[d] *= corr;
                    m = s;
                }
                float p = __expf(s - m);
                l += p;
#pragma unroll
                for (int c = 0; c < 16; c++) {
                    float4 vv = Vs[j * 16 + c];
                    acc[c * 4 + 0] += p * vv.x;
                    acc[c * 4 + 1] += p * vv.y;
                    acc[c * 4 + 2] += p * vv.z;
                    acc[c * 4 + 3] += p * vv.w;
                }
            }
        }
        __syncthreads();
    }

    float g = g_gates[(b * T_ + i) * 3 + MODE];
    float inv = g / l;
    float* op = g_attn + ((size_t)(b * T_ + i)) * C_ + h * HS_;
#pragma unroll
    for (int d = 0; d < 64; d++) {
        float val = acc[d] * inv;
        if (MODE == 0) op[d] = val;
        else op[d] += val;
    }
}

// ---------------- host launch ----------------
extern "C" void kernel_launch(void* const* d_in, const int* in_sizes, int n_in,
                              void* d_out, int out_size)
{
    const float* x  = (const float*)d_in[0];
    const float* Wq = (const float*)d_in[1];
    const float* bq = (const float*)d_in[2];
    const float* Wk = (const float*)d_in[3];
    const float* bk = (const float*)d_in[4];
    const float* Wv = (const float*)d_in[5];
    const float* bv = (const float*)d_in[6];
    const float* Wo = (const float*)d_in[7];
    const float* bo = (const float*)d_in[8];
    const float* Wg = (const float*)d_in[9];
    const float* bg = (const float*)d_in[10];
    float* out = (float*)d_out;

    float *qp, *kp, *vp, *ap;
    cudaGetSymbolAddress((void**)&qp, g_q);
    cudaGetSymbolAddress((void**)&kp, g_k);
    cudaGetSymbolAddress((void**)&vp, g_v);
    cudaGetSymbolAddress((void**)&ap, g_attn);

    dim3 ggrid(C_ / 128, (B_ * T_) / 128);
    sgemm_bias_kernel<<<ggrid, 256>>>(x, Wq, bq, qp, B_ * T_, C_, C_);
    sgemm_bias_kernel<<<ggrid, 256>>>(x, Wk, bk, kp, B_ * T_, C_, C_);
    sgemm_bias_kernel<<<ggrid, 256>>>(x, Wv, bv, vp, B_ * T_, C_, C_);

    gates_kernel<<<(B_ * T_ * 32) / 256, 256>>>(x, Wg, bg);
    blockmean_kernel<<<(B_ * H_ * NB_ * HS_) / 256, 256>>>();
    qbar_kernel<<<B_ * H_, 256>>>();
    topk_kernel<<<B_ * H_, 32>>>();
    gather_kernel<<<(B_ * H_ * NSEL_ * BLK_ * HS_) / 256, 256>>>();

    dim3 agrid(T_ / 128, H_, B_);
    attn_kernel<0><<<agrid, 128>>>();
    attn_kernel<1><<<agrid, 128>>>();
    attn_kernel<2><<<agrid, 128>>>();

    sgemm_bias_kernel<<<ggrid, 256>>>(ap, Wo, bo, out, B_ * T_, C_, C_);
}

// round 3
// speedup vs baseline: 1.3403x; 1.3403x over previous
#include <cuda_runtime.h>
#include <cuda_bf16.h>
#include <stdint.h>
#include <math.h>

typedef unsigned int u32;

#define B_  2
#define T_  2048
#define C_  1024
#define H_  16
#define HS_ 64
#define NB_ 32
#define BLK_ 64
#define NSEL_ 8
#define WSZ_ 128
#define M_  (B_*T_)

// ---------------- device scratch ----------------
__device__ float g_q[B_*T_*C_];
__device__ float g_k[B_*T_*C_];
__device__ float g_v[B_*T_*C_];
__device__ float g_attn[B_*T_*C_];
__device__ float g_gates[B_*T_*3];
__device__ float g_krep[B_*H_*NB_*HS_];
__device__ float g_vcmp[B_*H_*NB_*HS_];
__device__ float g_qbar[B_*H_*HS_];
__device__ int   g_topidx[B_*H_*NSEL_];
__device__ float g_selk[B_*H_*NSEL_*BLK_*HS_];
__device__ float g_selv[B_*H_*NSEL_*BLK_*HS_];

// bf16 split buffers (hi/lo) for GEMM operands
__device__ __nv_bfloat16 g_xh[M_*C_];
__device__ __nv_bfloat16 g_xl[M_*C_];
__device__ __nv_bfloat16 g_ah[M_*C_];
__device__ __nv_bfloat16 g_al[M_*C_];
__device__ __nv_bfloat16 g_wh[C_*C_];
__device__ __nv_bfloat16 g_wl[C_*C_];

// ---------------- fp32 -> bf16 hi/lo split ----------------
__global__ void split_kernel(const float* __restrict__ src,
                             __nv_bfloat16* __restrict__ hi,
                             __nv_bfloat16* __restrict__ lo, int n4)
{
    int i = blockIdx.x * blockDim.x + threadIdx.x;
    if (i >= n4) return;
    float4 v = ((const float4*)src)[i];
    __nv_bfloat16 h0 = __float2bfloat16(v.x);
    __nv_bfloat16 h1 = __float2bfloat16(v.y);
    __nv_bfloat16 h2 = __float2bfloat16(v.z);
    __nv_bfloat16 h3 = __float2bfloat16(v.w);
    __nv_bfloat16 l0 = __float2bfloat16(v.x - __bfloat162float(h0));
    __nv_bfloat16 l1 = __float2bfloat16(v.y - __bfloat162float(h1));
    __nv_bfloat16 l2 = __float2bfloat16(v.z - __bfloat162float(h2));
    __nv_bfloat16 l3 = __float2bfloat16(v.w - __bfloat162float(h3));
    __nv_bfloat162* hp = (__nv_bfloat162*)hi;
    __nv_bfloat162* lp = (__nv_bfloat162*)lo;
    hp[i*2]   = __halves2bfloat162(h0, h1);
    hp[i*2+1] = __halves2bfloat162(h2, h3);
    lp[i*2]   = __halves2bfloat162(l0, l1);
    lp[i*2+1] = __halves2bfloat162(l2, l3);
}

// ---------------- tensor-core helpers ----------------
__device__ __forceinline__ void ldsm_x4(u32* r, u32 addr) {
    asm volatile("ldmatrix.sync.aligned.m8n8.x4.shared.b16 {%0,%1,%2,%3}, [%4];"
        : "=r"(r[0]), "=r"(r[1]), "=r"(r[2]), "=r"(r[3]) : "r"(addr));
}
__device__ __forceinline__ void ldsm_x4_t(u32* r, u32 addr) {
    asm volatile("ldmatrix.sync.aligned.m8n8.x4.trans.shared.b16 {%0,%1,%2,%3}, [%4];"
        : "=r"(r[0]), "=r"(r[1]), "=r"(r[2]), "=r"(r[3]) : "r"(addr));
}
__device__ __forceinline__ void mma16816(float* d, const u32* a, const u32* b) {
    asm volatile(
        "mma.sync.aligned.m16n8k16.row.col.f32.bf16.bf16.f32 "
        "{%0,%1,%2,%3},{%4,%5,%6,%7},{%8,%9},{%0,%1,%2,%3};"
        : "+f"(d[0]), "+f"(d[1]), "+f"(d[2]), "+f"(d[3])
        : "r"(a[0]), "r"(a[1]), "r"(a[2]), "r"(a[3]), "r"(b[0]), "r"(b[1]));
}

#define BM 128
#define BN 128
#define BKK 32
#define APAD 8
#define BPAD 8

// ---------------- tensor-core bf16x3 GEMM: C = A@B + bias ----------------
__global__ void __launch_bounds__(256) gemm_bf16x3_kernel(
    const __nv_bfloat16* __restrict__ Ah, const __nv_bfloat16* __restrict__ Al,
    const __nv_bfloat16* __restrict__ Bh, const __nv_bfloat16* __restrict__ Bl,
    const float* __restrict__ bias, float* __restrict__ C,
    int M, int N, int K)
{
    __shared__ __nv_bfloat16 sAh[BM][BKK + APAD];
    __shared__ __nv_bfloat16 sAl[BM][BKK + APAD];
    __shared__ __nv_bfloat16 sBh[BKK][BN + BPAD];
    __shared__ __nv_bfloat16 sBl[BKK][BN + BPAD];

    int tid = threadIdx.x;
    int lane = tid & 31, warp = tid >> 5;
    int wm = warp >> 1, wn = warp & 1;          // 4x2 warps, warp tile 32x64
    int bm0 = blockIdx.y * BM, bn0 = blockIdx.x * BN;

    float acc[2][8][4];
#pragma unroll
    for (int mt = 0; mt < 2; mt++)
#pragma unroll
        for (int nt = 0; nt < 8; nt++)
#pragma unroll
            for (int r = 0; r < 4; r++) acc[mt][nt][r] = 0.f;

    for (int k0 = 0; k0 < K; k0 += BKK) {
#pragma unroll
        for (int j = 0; j < 2; j++) {
            int idx = tid + j * 256;
            int ar = idx >> 2, ac = (idx & 3) << 3;
            *(uint4*)&sAh[ar][ac] = *(const uint4*)&Ah[(size_t)(bm0 + ar) * K + k0 + ac];
            *(uint4*)&sAl[ar][ac] = *(const uint4*)&Al[(size_t)(bm0 + ar) * K + k0 + ac];
            int br = idx >> 4, bc = (idx & 15) << 3;
            *(uint4*)&sBh[br][bc] = *(const uint4*)&Bh[(size_t)(k0 + br) * N + bn0 + bc];
            *(uint4*)&sBl[br][bc] = *(const uint4*)&Bl[(size_t)(k0 + br) * N + bn0 + bc];
        }
        __syncthreads();

#pragma unroll
        for (int ks = 0; ks < 2; ks++) {
            int kk = ks * 16;
            u32 ah[2][4], al[2][4];
#pragma unroll
            for (int mt = 0; mt < 2; mt++) {
                int row = wm * 32 + mt * 16 + (lane & 15);
                int col = kk + ((lane >> 4) << 3);
                ldsm_x4(ah[mt], (u32)__cvta_generic_to_shared(&sAh[row][col]));
                ldsm_x4(al[mt], (u32)__cvta_generic_to_shared(&sAl[row][col]));
            }
#pragma unroll
            for (int np = 0; np < 4; np++) {
                int krow = kk + (lane & 7) + (lane & 8);
                int ncol = wn * 64 + np * 16 + ((lane >> 4) << 3);
                u32 bh[4], bl[4];
                ldsm_x4_t(bh, (u32)__cvta_generic_to_shared(&sBh[krow][ncol]));
                ldsm_x4_t(bl, (u32)__cvta_generic_to_shared(&sBl[krow][ncol]));
#pragma unroll
                for (int mt = 0; mt < 2; mt++) {
#pragma unroll
                    for (int t = 0; t < 2; t++) {
                        int nt = np * 2 + t;
                        mma16816(acc[mt][nt], ah[mt], &bh[t * 2]);  // hi*hi
                        mma16816(acc[mt][nt], ah[mt], &bl[t * 2]);  // hi*lo
                        mma16816(acc[mt][nt], al[mt], &bh[t * 2]);  // lo*hi
                    }
                }
            }
        }
        __syncthreads();
    }

    int grp = lane >> 2, tg = lane & 3;
#pragma unroll
    for (int mt = 0; mt < 2; mt++) {
#pragma unroll
        for (int nt = 0; nt < 8; nt++) {
            int row = bm0 + wm * 32 + mt * 16 + grp;
            int col = bn0 + wn * 64 + nt * 8 + tg * 2;
            float b0 = bias[col], b1 = bias[col + 1];
            float* c0 = C + (size_t)row * N + col;
            float* c1 = C + (size_t)(row + 8) * N + col;
            c0[0] = acc[mt][nt][0] + b0;
            c0[1] = acc[mt][nt][1] + b1;
            c1[0] = acc[mt][nt][2] + b0;
            c1[1] = acc[mt][nt][3] + b1;
        }
    }
}

// ---------------- gates = softmax(x @ Wg + bg), one warp per token ----------------
__global__ void gates_kernel(const float* __restrict__ x,
                             const float* __restrict__ Wg,
                             const float* __restrict__ bg)
{
    int gidx = blockIdx.x * blockDim.x + threadIdx.x;
    int w = gidx >> 5, lane = gidx & 31;
    if (w >= B_ * T_) return;
    const float* xr = x + (size_t)w * C_;
    float s0 = 0, s1 = 0, s2 = 0;
    for (int c = lane; c < C_; c += 32) {
        float xv = xr[c];
        s0 += xv * Wg[c * 3 + 0];
        s1 += xv * Wg[c * 3 + 1];
        s2 += xv * Wg[c * 3 + 2];
    }
#pragma unroll
    for (int o = 16; o; o >>= 1) {
        s0 += __shfl_xor_sync(0xffffffffu, s0, o);
        s1 += __shfl_xor_sync(0xffffffffu, s1, o);
        s2 += __shfl_xor_sync(0xffffffffu, s2, o);
    }
    if (lane == 0) {
        s0 += bg[0]; s1 += bg[1]; s2 += bg[2];
        float mx = fmaxf(s0, fmaxf(s1, s2));
        float e0 = __expf(s0 - mx), e1 = __expf(s1 - mx), e2 = __expf(s2 - mx);
        float inv = 1.f / (e0 + e1 + e2);
        g_gates[w * 3 + 0] = e0 * inv;
        g_gates[w * 3 + 1] = e1 * inv;
        g_gates[w * 3 + 2] = e2 * inv;
    }
}

// ---------------- per-block mean of K and V ----------------
__global__ void blockmean_kernel()
{
    int idx = blockIdx.x * blockDim.x + threadIdx.x;
    if (idx >= B_ * H_ * NB_ * HS_) return;
    int d = idx & 63;
    int n = (idx >> 6) & 31;
    int h = (idx >> 11) & 15;
    int b = idx >> 15;
    const float* kp = g_k + ((size_t)(b * T_ + n * BLK_)) * C_ + h * HS_ + d;
    const float* vp = g_v + ((size_t)(b * T_ + n * BLK_)) * C_ + h * HS_ + d;
    float sk = 0.f, sv = 0.f;
    for (int j = 0; j < BLK_; j++) {
        sk += kp[(size_t)j * C_];
        sv += vp[(size_t)j * C_];
    }
    g_krep[idx] = sk * (1.f / BLK_);
    g_vcmp[idx] = sv * (1.f / BLK_);
}

// ---------------- qbar ----------------
__global__ void qbar_kernel()
{
    int b = blockIdx.x >> 4, h = blockIdx.x & 15;
    int warp = threadIdx.x >> 5, lane = threadIdx.x & 31;
    float a0 = 0.f, a1 = 0.f;
    for (int t = warp; t < T_; t += 8) {
        const float* qr = g_q + ((size_t)(b * T_ + t)) * C_ + h * HS_;
        float x0 = qr[lane], x1 = qr[lane + 32];
        float ss = x0 * x0 + x1 * x1;
#pragma unroll
        for (int o = 16; o; o >>= 1) ss += __shfl_xor_sync(0xffffffffu, ss, o);
        float inv = 1.f / fmaxf(sqrtf(ss), 1e-8f);
        a0 += x0 * inv;
        a1 += x1 * inv;
    }
    __shared__ float acc[64];
    if (threadIdx.x < 64) acc[threadIdx.x] = 0.f;
    __syncthreads();
    atomicAdd(&acc[lane], a0);
    atomicAdd(&acc[lane + 32], a1);
    __syncthreads();
    if (threadIdx.x < 64) g_qbar[blockIdx.x * 64 + threadIdx.x] = acc[threadIdx.x];
}

// ---------------- top-8 (stable, lowest index wins ties) ----------------
__global__ void topk_kernel()
{
    int bh = blockIdx.x;
    int n = threadIdx.x;
    const float* kr = g_krep + ((size_t)bh * NB_ + n) * HS_;
    const float* qb = g_qbar + (size_t)bh * HS_;
    float dot = 0.f, ss = 0.f;
    for (int d = 0; d < HS_; d++) {
        float kv = kr[d];
        dot += kv * qb[d];
        ss += kv * kv;
    }
    float score = dot / fmaxf(sqrtf(ss), 1e-8f);
    __shared__ float sc[NB_];
    sc[n] = score;
    __syncthreads();
    if (n == 0) {
        bool used[NB_];
        for (int m = 0; m < NB_; m++) used[m] = false;
        for (int s = 0; s < NSEL_; s++) {
            float best = -1e30f; int bi = 0;
            for (int m = 0; m < NB_; m++)
                if (!used[m] && sc[m] > best) { best = sc[m]; bi = m; }
            used[bi] = true;
            g_topidx[bh * NSEL_ + s] = bi;
        }
    }
}

// ---------------- gather selected K/V ----------------
__global__ void gather_kernel()
{
    int idx = blockIdx.x * blockDim.x + threadIdx.x;
    if (idx >= B_ * H_ * NSEL_ * BLK_ * HS_) return;
    int d = idx & 63;
    int s = (idx >> 6) & 511;
    int h = (idx >> 15) & 15;
    int b = idx >> 19;
    int blk = g_topidx[(b * H_ + h) * NSEL_ + (s >> 6)];
    int row = blk * BLK_ + (s & 63);
    size_t src = ((size_t)(b * T_ + row)) * C_ + h * HS_ + d;
    g_selk[idx] = g_k[src];
    g_selv[idx] = g_v[src];
}

// ---------------- attention (3 modes, online softmax, 1 thread = 1 query) ----------------
template <int MODE>
__global__ void __launch_bounds__(128) attn_kernel()
{
    int q0 = blockIdx.x * 128;
    int h = blockIdx.y, b = blockIdx.z;
    int i = q0 + threadIdx.x;

    float qv[64];
    const float* qr = g_q + ((size_t)(b * T_ + i)) * C_ + h * HS_;
#pragma unroll
    for (int c = 0; c < 16; c++) *(float4*)&qv[c * 4] = *(const float4*)(qr + c * 4);

    __shared__ float4 Ks[64 * 16];
    __shared__ float4 Vs[64 * 16];

    float m = -1e30f, l = 0.f;
    float acc[64];
#pragma unroll
    for (int d = 0; d < 64; d++) acc[d] = 0.f;
    const float scale = 0.125f;

    int kt0, kt1, nrows;
    if (MODE == 0) { kt0 = (q0 > WSZ_ ? (q0 - WSZ_) >> 6 : 0); kt1 = (q0 + 127) >> 6; nrows = 64; }
    else if (MODE == 1) { kt0 = 0; int m1 = (q0 + 127) >> 6; kt1 = (m1 < 7 ? m1 : 7); nrows = 64; }
    else { kt0 = 0; kt1 = 0; nrows = 32; }

    for (int kt = kt0; kt <= kt1; kt++) {
        const float* ksrc; const float* vsrc; int kstride;
        if (MODE == 0) {
            ksrc = g_k + ((size_t)(b * T_ + kt * 64)) * C_ + h * HS_;
            vsrc = g_v + ((size_t)(b * T_ + kt * 64)) * C_ + h * HS_;
            kstride = C_;
        } else if (MODE == 1) {
            ksrc = g_selk + ((size_t)((b * H_ + h) * 512 + kt * 64)) * HS_;
            vsrc = g_selv + ((size_t)((b * H_ + h) * 512 + kt * 64)) * HS_;
            kstride = HS_;
        } else {
            ksrc = g_krep + ((size_t)(b * H_ + h) * NB_) * HS_;
            vsrc = g_vcmp + ((size_t)(b * H_ + h) * NB_) * HS_;
            kstride = HS_;
        }
        for (int idx = threadIdx.x; idx < nrows * 16; idx += 128) {
            int r = idx >> 4, c = idx & 15;
            Ks[idx] = *(const float4*)(ksrc + (size_t)r * kstride + c * 4);
            Vs[idx] = *(const float4*)(vsrc + (size_t)r * kstride + c * 4);
        }
        __syncthreads();

        for (int j = 0; j < nrows; j++) {
            int jj = kt * 64 + j;
            bool valid = (jj <= i);
            if (MODE == 0) valid = valid && (i - jj <= WSZ_);
            if (valid) {
                float s = 0.f;
#pragma unroll
                for (int c = 0; c < 16; c++) {
                    float4 kk = Ks[j * 16 + c];
                    s += qv[c * 4] * kk.x + qv[c * 4 + 1] * kk.y
                       + qv[c * 4 + 2] * kk.z + qv[c * 4 + 3] * kk.w;
                }
                s *= scale;
                if (s > m) {
                    float corr = __expf(m - s);
                    l *= corr;
#pragma unroll
                    for (int d = 0; d < 64; d++) acc[d] *= corr;
                    m = s;
                }
                float p = __expf(s - m);
                l += p;
#pragma unroll
                for (int c = 0; c < 16; c++) {
                    float4 vv = Vs[j * 16 + c];
                    acc[c * 4 + 0] += p * vv.x;
                    acc[c * 4 + 1] += p * vv.y;
                    acc[c * 4 + 2] += p * vv.z;
                    acc[c * 4 + 3] += p * vv.w;
                }
            }
        }
        __syncthreads();
    }

    float g = g_gates[(b * T_ + i) * 3 + MODE];
    float inv = g / l;
    float* op = g_attn + ((size_t)(b * T_ + i)) * C_ + h * HS_;
#pragma unroll
    for (int d = 0; d < 64; d++) {
        float val = acc[d] * inv;
        if (MODE == 0) op[d] = val;
        else op[d] += val;
    }
}

// ---------------- host launch ----------------
extern "C" void kernel_launch(void* const* d_in, const int* in_sizes, int n_in,
                              void* d_out, int out_size)
{
    const float* x  = (const float*)d_in[0];
    const float* Wq = (const float*)d_in[1];
    const float* bq = (const float*)d_in[2];
    const float* Wk = (const float*)d_in[3];
    const float* bk = (const float*)d_in[4];
    const float* Wv = (const float*)d_in[5];
    const float* bv = (const float*)d_in[6];
    const float* Wo = (const float*)d_in[7];
    const float* bo = (const float*)d_in[8];
    const float* Wg = (const float*)d_in[9];
    const float* bg = (const float*)d_in[10];
    float* out = (float*)d_out;

    float *qp, *kp, *vp, *ap;
    cudaGetSymbolAddress((void**)&qp, g_q);
    cudaGetSymbolAddress((void**)&kp, g_k);
    cudaGetSymbolAddress((void**)&vp, g_v);
    cudaGetSymbolAddress((void**)&ap, g_attn);
    __nv_bfloat16 *xh, *xl, *ah, *al, *wh, *wl;
    cudaGetSymbolAddress((void**)&xh, g_xh);
    cudaGetSymbolAddress((void**)&xl, g_xl);
    cudaGetSymbolAddress((void**)&ah, g_ah);
    cudaGetSymbolAddress((void**)&al, g_al);
    cudaGetSymbolAddress((void**)&wh, g_wh);
    cudaGetSymbolAddress((void**)&wl, g_wl);

    const int nX4 = (M_ * C_) / 4;
    const int nW4 = (C_ * C_) / 4;

    dim3 ggrid(C_ / 128, M_ / 128);

    // split activations once (reused for Q/K/V GEMMs)
    split_kernel<<<(nX4 + 255) / 256, 256>>>(x, xh, xl, nX4);

    split_kernel<<<(nW4 + 255) / 256, 256>>>(Wq, wh, wl, nW4);
    gemm_bf16x3_kernel<<<ggrid, 256>>>(xh, xl, wh, wl, bq, qp, M_, C_, C_);
    split_kernel<<<(nW4 + 255) / 256, 256>>>(Wk, wh, wl, nW4);
    gemm_bf16x3_kernel<<<ggrid, 256>>>(xh, xl, wh, wl, bk, kp, M_, C_, C_);
    split_kernel<<<(nW4 + 255) / 256, 256>>>(Wv, wh, wl, nW4);
    gemm_bf16x3_kernel<<<ggrid, 256>>>(xh, xl, wh, wl, bv, vp, M_, C_, C_);

    gates_kernel<<<(B_ * T_ * 32) / 256, 256>>>(x, Wg, bg);
    blockmean_kernel<<<(B_ * H_ * NB_ * HS_) / 256, 256>>>();
    qbar_kernel<<<B_ * H_, 256>>>();
    topk_kernel<<<B_ * H_, 32>>>();
    gather_kernel<<<(B_ * H_ * NSEL_ * BLK_ * HS_) / 256, 256>>>();

    dim3 agrid(T_ / 128, H_, B_);
    attn_kernel<0><<<agrid, 128>>>();
    attn_kernel<1><<<agrid, 128>>>();
    attn_kernel<2><<<agrid, 128>>>();

    // output projection
    split_kernel<<<(nX4 + 255) / 256, 256>>>(ap, ah, al, nX4);
    split_kernel<<<(nW4 + 255) / 256, 256>>>(Wo, wh, wl, nW4);
    gemm_bf16x3_kernel<<<ggrid, 256>>>(ah, al, wh, wl, bo, out, M_, C_, C_);
}

// round 4
// speedup vs baseline: 2.1767x; 1.6240x over previous
#include <cuda_runtime.h>
#include <cuda_bf16.h>
#include <stdint.h>
#include <math.h>

typedef unsigned int u32;

#define B_  2
#define T_  2048
#define C_  1024
#define H_  16
#define HS_ 64
#define NB_ 32
#define BLK_ 64
#define NSEL_ 8
#define WSZ_ 128
#define M_  (B_*T_)

// ---------------- device scratch ----------------
__device__ float g_q[B_*T_*C_];
__device__ float g_k[B_*T_*C_];
__device__ float g_v[B_*T_*C_];
__device__ float g_attn[B_*T_*C_];
__device__ float g_gates[B_*T_*3];
__device__ float g_krep[B_*H_*NB_*HS_];
__device__ float g_vcmp[B_*H_*NB_*HS_];
__device__ float g_qbar[B_*H_*HS_];
__device__ int   g_topidx[B_*H_*NSEL_];
__device__ float g_selk[B_*H_*NSEL_*BLK_*HS_];
__device__ float g_selv[B_*H_*NSEL_*BLK_*HS_];

// bf16 split buffers (hi/lo) for GEMM operands
__device__ __nv_bfloat16 g_xh[M_*C_];
__device__ __nv_bfloat16 g_xl[M_*C_];
__device__ __nv_bfloat16 g_ah[M_*C_];
__device__ __nv_bfloat16 g_al[M_*C_];
__device__ __nv_bfloat16 g_wh[C_*C_];
__device__ __nv_bfloat16 g_wl[C_*C_];

// ---------------- fp32 -> bf16 hi/lo split ----------------
__global__ void split_kernel(const float* __restrict__ src,
                             __nv_bfloat16* __restrict__ hi,
                             __nv_bfloat16* __restrict__ lo, int n4)
{
    int i = blockIdx.x * blockDim.x + threadIdx.x;
    if (i >= n4) return;
    float4 v = ((const float4*)src)[i];
    __nv_bfloat16 h0 = __float2bfloat16(v.x);
    __nv_bfloat16 h1 = __float2bfloat16(v.y);
    __nv_bfloat16 h2 = __float2bfloat16(v.z);
    __nv_bfloat16 h3 = __float2bfloat16(v.w);
    __nv_bfloat16 l0 = __float2bfloat16(v.x - __bfloat162float(h0));
    __nv_bfloat16 l1 = __float2bfloat16(v.y - __bfloat162float(h1));
    __nv_bfloat16 l2 = __float2bfloat16(v.z - __bfloat162float(h2));
    __nv_bfloat16 l3 = __float2bfloat16(v.w - __bfloat162float(h3));
    __nv_bfloat162* hp = (__nv_bfloat162*)hi;
    __nv_bfloat162* lp = (__nv_bfloat162*)lo;
    hp[i*2]   = __halves2bfloat162(h0, h1);
    hp[i*2+1] = __halves2bfloat162(h2, h3);
    lp[i*2]   = __halves2bfloat162(l0, l1);
    lp[i*2+1] = __halves2bfloat162(l2, l3);
}

// ---------------- tensor-core helpers ----------------
__device__ __forceinline__ void ldsm_x4(u32* r, u32 addr) {
    asm volatile("ldmatrix.sync.aligned.m8n8.x4.shared.b16 {%0,%1,%2,%3}, [%4];"
        : "=r"(r[0]), "=r"(r[1]), "=r"(r[2]), "=r"(r[3]) : "r"(addr));
}
__device__ __forceinline__ void ldsm_x4_t(u32* r, u32 addr) {
    asm volatile("ldmatrix.sync.aligned.m8n8.x4.trans.shared.b16 {%0,%1,%2,%3}, [%4];"
        : "=r"(r[0]), "=r"(r[1]), "=r"(r[2]), "=r"(r[3]) : "r"(addr));
}
__device__ __forceinline__ void mma16816(float* d, const u32* a, const u32* b) {
    asm volatile(
        "mma.sync.aligned.m16n8k16.row.col.f32.bf16.bf16.f32 "
        "{%0,%1,%2,%3},{%4,%5,%6,%7},{%8,%9},{%0,%1,%2,%3};"
        : "+f"(d[0]), "+f"(d[1]), "+f"(d[2]), "+f"(d[3])
        : "r"(a[0]), "r"(a[1]), "r"(a[2]), "r"(a[3]), "r"(b[0]), "r"(b[1]));
}
__device__ __forceinline__ u32 pack_hi2(float a, float b) {
    __nv_bfloat162 t = __halves2bfloat162(__float2bfloat16(a), __float2bfloat16(b));
    return *(u32*)&t;
}
__device__ __forceinline__ u32 pack_lo2(float a, float b) {
    __nv_bfloat16 ha = __float2bfloat16(a), hb = __float2bfloat16(b);
    __nv_bfloat162 t = __halves2bfloat162(
        __float2bfloat16(a - __bfloat162float(ha)),
        __float2bfloat16(b - __bfloat162float(hb)));
    return *(u32*)&t;
}

#define BM 128
#define BN 128
#define BKK 32
#define APAD 8
#define BPAD 8

// ---------------- tensor-core bf16x3 GEMM: C = A@B + bias ----------------
__global__ void __launch_bounds__(256) gemm_bf16x3_kernel(
    const __nv_bfloat16* __restrict__ Ah, const __nv_bfloat16* __restrict__ Al,
    const __nv_bfloat16* __restrict__ Bh, const __nv_bfloat16* __restrict__ Bl,
    const float* __restrict__ bias, float* __restrict__ C,
    int M, int N, int K)
{
    __shared__ __nv_bfloat16 sAh[BM][BKK + APAD];
    __shared__ __nv_bfloat16 sAl[BM][BKK + APAD];
    __shared__ __nv_bfloat16 sBh[BKK][BN + BPAD];
    __shared__ __nv_bfloat16 sBl[BKK][BN + BPAD];

    int tid = threadIdx.x;
    int lane = tid & 31, warp = tid >> 5;
    int wm = warp >> 1, wn = warp & 1;
    int bm0 = blockIdx.y * BM, bn0 = blockIdx.x * BN;

    float acc[2][8][4];
#pragma unroll
    for (int mt = 0; mt < 2; mt++)
#pragma unroll
        for (int nt = 0; nt < 8; nt++)
#pragma unroll
            for (int r = 0; r < 4; r++) acc[mt][nt][r] = 0.f;

    for (int k0 = 0; k0 < K; k0 += BKK) {
#pragma unroll
        for (int j = 0; j < 2; j++) {
            int idx = tid + j * 256;
            int ar = idx >> 2, ac = (idx & 3) << 3;
            *(uint4*)&sAh[ar][ac] = *(const uint4*)&Ah[(size_t)(bm0 + ar) * K + k0 + ac];
            *(uint4*)&sAl[ar][ac] = *(const uint4*)&Al[(size_t)(bm0 + ar) * K + k0 + ac];
            int br = idx >> 4, bc = (idx & 15) << 3;
            *(uint4*)&sBh[br][bc] = *(const uint4*)&Bh[(size_t)(k0 + br) * N + bn0 + bc];
            *(uint4*)&sBl[br][bc] = *(const uint4*)&Bl[(size_t)(k0 + br) * N + bn0 + bc];
        }
        __syncthreads();

#pragma unroll
        for (int ks = 0; ks < 2; ks++) {
            int kk = ks * 16;
            u32 ah[2][4], al[2][4];
#pragma unroll
            for (int mt = 0; mt < 2; mt++) {
                int row = wm * 32 + mt * 16 + (lane & 15);
                int col = kk + ((lane >> 4) << 3);
                ldsm_x4(ah[mt], (u32)__cvta_generic_to_shared(&sAh[row][col]));
                ldsm_x4(al[mt], (u32)__cvta_generic_to_shared(&sAl[row][col]));
            }
#pragma unroll
            for (int np = 0; np < 4; np++) {
                int krow = kk + (lane & 7) + (lane & 8);
                int ncol = wn * 64 + np * 16 + ((lane >> 4) << 3);
                u32 bh[4], bl[4];
                ldsm_x4_t(bh, (u32)__cvta_generic_to_shared(&sBh[krow][ncol]));
                ldsm_x4_t(bl, (u32)__cvta_generic_to_shared(&sBl[krow][ncol]));
#pragma unroll
                for (int mt = 0; mt < 2; mt++) {
#pragma unroll
                    for (int t = 0; t < 2; t++) {
                        int nt = np * 2 + t;
                        mma16816(acc[mt][nt], ah[mt], &bh[t * 2]);
                        mma16816(acc[mt][nt], ah[mt], &bl[t * 2]);
                        mma16816(acc[mt][nt], al[mt], &bh[t * 2]);
                    }
                }
            }
        }
        __syncthreads();
    }

    int grp = lane >> 2, tg = lane & 3;
#pragma unroll
    for (int mt = 0; mt < 2; mt++) {
#pragma unroll
        for (int nt = 0; nt < 8; nt++) {
            int row = bm0 + wm * 32 + mt * 16 + grp;
            int col = bn0 + wn * 64 + nt * 8 + tg * 2;
            float b0 = bias[col], b1 = bias[col + 1];
            float* c0 = C + (size_t)row * N + col;
            float* c1 = C + (size_t)(row + 8) * N + col;
            c0[0] = acc[mt][nt][0] + b0;
            c0[1] = acc[mt][nt][1] + b1;
            c1[0] = acc[mt][nt][2] + b0;
            c1[1] = acc[mt][nt][3] + b1;
        }
    }
}

// ---------------- gates ----------------
__global__ void gates_kernel(const float* __restrict__ x,
                             const float* __restrict__ Wg,
                             const float* __restrict__ bg)
{
    int gidx = blockIdx.x * blockDim.x + threadIdx.x;
    int w = gidx >> 5, lane = gidx & 31;
    if (w >= B_ * T_) return;
    const float* xr = x + (size_t)w * C_;
    float s0 = 0, s1 = 0, s2 = 0;
    for (int c = lane; c < C_; c += 32) {
        float xv = xr[c];
        s0 += xv * Wg[c * 3 + 0];
        s1 += xv * Wg[c * 3 + 1];
        s2 += xv * Wg[c * 3 + 2];
    }
#pragma unroll
    for (int o = 16; o; o >>= 1) {
        s0 += __shfl_xor_sync(0xffffffffu, s0, o);
        s1 += __shfl_xor_sync(0xffffffffu, s1, o);
        s2 += __shfl_xor_sync(0xffffffffu, s2, o);
    }
    if (lane == 0) {
        s0 += bg[0]; s1 += bg[1]; s2 += bg[2];
        float mx = fmaxf(s0, fmaxf(s1, s2));
        float e0 = __expf(s0 - mx), e1 = __expf(s1 - mx), e2 = __expf(s2 - mx);
        float inv = 1.f / (e0 + e1 + e2);
        g_gates[w * 3 + 0] = e0 * inv;
        g_gates[w * 3 + 1] = e1 * inv;
        g_gates[w * 3 + 2] = e2 * inv;
    }
}

// ---------------- per-block mean of K and V ----------------
__global__ void blockmean_kernel()
{
    int idx = blockIdx.x * blockDim.x + threadIdx.x;
    if (idx >= B_ * H_ * NB_ * HS_) return;
    int d = idx & 63;
    int n = (idx >> 6) & 31;
    int h = (idx >> 11) & 15;
    int b = idx >> 15;
    const float* kp = g_k + ((size_t)(b * T_ + n * BLK_)) * C_ + h * HS_ + d;
    const float* vp = g_v + ((size_t)(b * T_ + n * BLK_)) * C_ + h * HS_ + d;
    float sk = 0.f, sv = 0.f;
    for (int j = 0; j < BLK_; j++) {
        sk += kp[(size_t)j * C_];
        sv += vp[(size_t)j * C_];
    }
    g_krep[idx] = sk * (1.f / BLK_);
    g_vcmp[idx] = sv * (1.f / BLK_);
}

// ---------------- qbar ----------------
__global__ void qbar_kernel()
{
    int b = blockIdx.x >> 4, h = blockIdx.x & 15;
    int warp = threadIdx.x >> 5, lane = threadIdx.x & 31;
    float a0 = 0.f, a1 = 0.f;
    for (int t = warp; t < T_; t += 8) {
        const float* qr = g_q + ((size_t)(b * T_ + t)) * C_ + h * HS_;
        float x0 = qr[lane], x1 = qr[lane + 32];
        float ss = x0 * x0 + x1 * x1;
#pragma unroll
        for (int o = 16; o; o >>= 1) ss += __shfl_xor_sync(0xffffffffu, ss, o);
        float inv = 1.f / fmaxf(sqrtf(ss), 1e-8f);
        a0 += x0 * inv;
        a1 += x1 * inv;
    }
    __shared__ float acc[64];
    if (threadIdx.x < 64) acc[threadIdx.x] = 0.f;
    __syncthreads();
    atomicAdd(&acc[lane], a0);
    atomicAdd(&acc[lane + 32], a1);
    __syncthreads();
    if (threadIdx.x < 64) g_qbar[blockIdx.x * 64 + threadIdx.x] = acc[threadIdx.x];
}

// ---------------- top-8 ----------------
__global__ void topk_kernel()
{
    int bh = blockIdx.x;
    int n = threadIdx.x;
    const float* kr = g_krep + ((size_t)bh * NB_ + n) * HS_;
    const float* qb = g_qbar + (size_t)bh * HS_;
    float dot = 0.f, ss = 0.f;
    for (int d = 0; d < HS_; d++) {
        float kv = kr[d];
        dot += kv * qb[d];
        ss += kv * kv;
    }
    float score = dot / fmaxf(sqrtf(ss), 1e-8f);
    __shared__ float sc[NB_];
    sc[n] = score;
    __syncthreads();
    if (n == 0) {
        bool used[NB_];
        for (int m = 0; m < NB_; m++) used[m] = false;
        for (int s = 0; s < NSEL_; s++) {
            float best = -1e30f; int bi = 0;
            for (int m = 0; m < NB_; m++)
                if (!used[m] && sc[m] > best) { best = sc[m]; bi = m; }
            used[bi] = true;
            g_topidx[bh * NSEL_ + s] = bi;
        }
    }
}

// ---------------- gather selected K/V ----------------
__global__ void gather_kernel()
{
    int idx = blockIdx.x * blockDim.x + threadIdx.x;
    if (idx >= B_ * H_ * NSEL_ * BLK_ * HS_) return;
    int d = idx & 63;
    int s = (idx >> 6) & 511;
    int h = (idx >> 15) & 15;
    int b = idx >> 19;
    int blk = g_topidx[(b * H_ + h) * NSEL_ + (s >> 6)];
    int row = blk * BLK_ + (s & 63);
    size_t src = ((size_t)(b * T_ + row)) * C_ + h * HS_ + d;
    g_selk[idx] = g_k[src];
    g_selv[idx] = g_v[src];
}

// ---------------- tensor-core flash attention ----------------
// Block = 64 queries of one (b,h); 4 warps x 16 rows. K/V fp32 -> bf16 hi/lo
// in smem; S = QK^T via bf16x3 mma; online softmax on fragments; PV bf16x3.
// MODE 0: sliding (jj<=i && i-jj<=128), MODE 1: selected (jj<=i over concat),
// MODE 2: compressed (block jj<=i), NT = key n-tiles per smem tile.
template <int MODE, int NT>
__global__ void __launch_bounds__(128) fattn_kernel()
{
    const int qt = blockIdx.x;
    const int h = blockIdx.y, b = blockIdx.z;
    const int q0 = qt * 64;
    const int lane = threadIdx.x & 31, warp = threadIdx.x >> 5;
    const int g = lane >> 2, tg = lane & 3;
    const int i0 = q0 + warp * 16 + g;      // row 0 of this thread
    const int i1 = i0 + 8;                  // row 1

    const int KROWS = NT * 8;

    __shared__ __align__(16) __nv_bfloat16 sKh[64][72];
    __shared__ __align__(16) __nv_bfloat16 sKl[64][72];
    __shared__ __align__(16) __nv_bfloat16 sVh[64][72];
    __shared__ __align__(16) __nv_bfloat16 sVl[64][72];

    // ---- load Q fragments (A, m16k16, 4 k-steps), hi/lo ----
    u32 qh[4][4], ql[4][4];
    {
        const float* qr0 = g_q + ((size_t)(b * T_ + i0)) * C_ + h * HS_;
        const float* qr1 = g_q + ((size_t)(b * T_ + i1)) * C_ + h * HS_;
#pragma unroll
        for (int kk = 0; kk < 4; kk++) {
            int c = kk * 16 + tg * 2;
            qh[kk][0] = pack_hi2(qr0[c], qr0[c + 1]);
            ql[kk][0] = pack_lo2(qr0[c], qr0[c + 1]);
            qh[kk][1] = pack_hi2(qr1[c], qr1[c + 1]);
            ql[kk][1] = pack_lo2(qr1[c], qr1[c + 1]);
            qh[kk][2] = pack_hi2(qr0[c + 8], qr0[c + 9]);
            ql[kk][2] = pack_lo2(qr0[c + 8], qr0[c + 9]);
            qh[kk][3] = pack_hi2(qr1[c + 8], qr1[c + 9]);
            ql[kk][3] = pack_lo2(qr1[c + 8], qr1[c + 9]);
        }
    }

    float O[8][4];
#pragma unroll
    for (int nt = 0; nt < 8; nt++)
#pragma unroll
        for (int r = 0; r < 4; r++) O[nt][r] = 0.f;
    float m0 = -1e30f, m1 = -1e30f, l0 = 0.f, l1 = 0.f;

    int kt0, kt1;
    if (MODE == 0) { kt0 = (qt >= 2 ? qt - 2 : 0); kt1 = qt; }
    else if (MODE == 1) { kt0 = 0; kt1 = (qt < 7 ? qt : 7); }
    else { kt0 = 0; kt1 = 0; }

    for (int kt = kt0; kt <= kt1; kt++) {
        // ---- stage K/V tile to smem (fp32 -> bf16 hi/lo) ----
        const float* ksrc; const float* vsrc; int kstride;
        if (MODE == 0) {
            ksrc = g_k + ((size_t)(b * T_ + kt * 64)) * C_ + h * HS_;
            vsrc = g_v + ((size_t)(b * T_ + kt * 64)) * C_ + h * HS_;
            kstride = C_;
        } else if (MODE == 1) {
            ksrc = g_selk + ((size_t)((b * H_ + h) * 512 + kt * 64)) * HS_;
            vsrc = g_selv + ((size_t)((b * H_ + h) * 512 + kt * 64)) * HS_;
            kstride = HS_;
        } else {
            ksrc = g_krep + ((size_t)(b * H_ + h) * NB_) * HS_;
            vsrc = g_vcmp + ((size_t)(b * H_ + h) * NB_) * HS_;
            kstride = HS_;
        }
        for (int idx = threadIdx.x; idx < KROWS * 16; idx += 128) {
            int r = idx >> 4, c = (idx & 15) * 4;
            float4 kv = *(const float4*)(ksrc + (size_t)r * kstride + c);
            float4 vv = *(const float4*)(vsrc + (size_t)r * kstride + c);
            __nv_bfloat16 h0 = __float2bfloat16(kv.x), h1 = __float2bfloat16(kv.y);
            __nv_bfloat16 h2 = __float2bfloat16(kv.z), h3 = __float2bfloat16(kv.w);
            sKh[r][c] = h0; sKh[r][c+1] = h1; sKh[r][c+2] = h2; sKh[r][c+3] = h3;
            sKl[r][c]   = __float2bfloat16(kv.x - __bfloat162float(h0));
            sKl[r][c+1] = __float2bfloat16(kv.y - __bfloat162float(h1));
            sKl[r][c+2] = __float2bfloat16(kv.z - __bfloat162float(h2));
            sKl[r][c+3] = __float2bfloat16(kv.w - __bfloat162float(h3));
            h0 = __float2bfloat16(vv.x); h1 = __float2bfloat16(vv.y);
            h2 = __float2bfloat16(vv.z); h3 = __float2bfloat16(vv.w);
            sVh[r][c] = h0; sVh[r][c+1] = h1; sVh[r][c+2] = h2; sVh[r][c+3] = h3;
            sVl[r][c]   = __float2bfloat16(vv.x - __bfloat162float(h0));
            sVl[r][c+1] = __float2bfloat16(vv.y - __bfloat162float(h1));
            sVl[r][c+2] = __float2bfloat16(vv.z - __bfloat162float(h2));
            sVl[r][c+3] = __float2bfloat16(vv.w - __bfloat162float(h3));
        }
        __syncthreads();

        // ---- S = Q K^T (bf16x3) ----
        float S[NT][4];
#pragma unroll
        for (int nt = 0; nt < NT; nt++)
#pragma unroll
            for (int r = 0; r < 4; r++) S[nt][r] = 0.f;

#pragma unroll
        for (int kk = 0; kk < 4; kk++) {
#pragma unroll
            for (int ntp = 0; ntp < NT / 2; ntp++) {
                // B fragments for keys [ntp*16, +16), d [kk*16, +16)
                int row = ntp * 16 + ((lane >> 4) << 3) + (lane & 7);
                int col = kk * 16 + (((lane >> 3) & 1) << 3);
                u32 kh[4], kl[4];
                ldsm_x4(kh, (u32)__cvta_generic_to_shared(&sKh[row][col]));
                ldsm_x4(kl, (u32)__cvta_generic_to_shared(&sKl[row][col]));
#pragma unroll
                for (int t = 0; t < 2; t++) {
                    int nt = ntp * 2 + t;
                    mma16816(S[nt], qh[kk], &kh[t * 2]);
                    mma16816(S[nt], qh[kk], &kl[t * 2]);
                    mma16816(S[nt], ql[kk], &kh[t * 2]);
                }
            }
        }

        // ---- mask + scale ----
        const int tilebase = kt * 64;
#pragma unroll
        for (int nt = 0; nt < NT; nt++) {
            int c0 = tilebase + nt * 8 + tg * 2;
            int c1 = c0 + 1;
            bool v00 = (c0 <= i0), v01 = (c1 <= i0), v10 = (c0 <= i1), v11 = (c1 <= i1);
            if (MODE == 0) {
                v00 = v00 && (i0 - c0 <= WSZ_);
                v01 = v01 && (i0 - c1 <= WSZ_);
                v10 = v10 && (i1 - c0 <= WSZ_);
                v11 = v11 && (i1 - c1 <= WSZ_);
            }
            S[nt][0] = v00 ? S[nt][0] * 0.125f : -1e30f;
            S[nt][1] = v01 ? S[nt][1] * 0.125f : -1e30f;
            S[nt][2] = v10 ? S[nt][2] * 0.125f : -1e30f;
            S[nt][3] = v11 ? S[nt][3] * 0.125f : -1e30f;
        }

        // ---- row max ----
        float mx0 = -1e30f, mx1 = -1e30f;
#pragma unroll
        for (int nt = 0; nt < NT; nt++) {
            mx0 = fmaxf(mx0, fmaxf(S[nt][0], S[nt][1]));
            mx1 = fmaxf(mx1, fmaxf(S[nt][2], S[nt][3]));
        }
        mx0 = fmaxf(mx0, __shfl_xor_sync(0xffffffffu, mx0, 1));
        mx0 = fmaxf(mx0, __shfl_xor_sync(0xffffffffu, mx0, 2));
        mx1 = fmaxf(mx1, __shfl_xor_sync(0xffffffffu, mx1, 1));
        mx1 = fmaxf(mx1, __shfl_xor_sync(0xffffffffu, mx1, 2));

        float mn0 = fmaxf(m0, mx0), mn1 = fmaxf(m1, mx1);
        float sc0 = __expf(m0 - mn0), sc1 = __expf(m1 - mn1);
        m0 = mn0; m1 = mn1;

        // ---- P = exp(S - m), row sums ----
        float la0 = 0.f, la1 = 0.f;
#pragma unroll
        for (int nt = 0; nt < NT; nt++) {
            S[nt][0] = __expf(S[nt][0] - mn0);
            S[nt][1] = __expf(S[nt][1] - mn1 + (mn1 - mn0) - (mn1 - mn0)); // placeholder avoided below
            S[nt][1] = __expf(0.f); // overwritten below
            S[nt][1] = 0.f;
            la0 += 0.f;
            la1 += 0.f;
        }
        // (recompute cleanly; the above no-op block is replaced)
        // NOTE: do exp properly:
        la0 = 0.f; la1 = 0.f;
#pragma unroll
        for (int nt = 0; nt < NT; nt++) {
            // S[nt][0] already exp'ed vs mn0 above; redo 1..3 consistently:
            // S[nt][0] holds exp already; compute the rest from masked values is lost,
            // so this path must not be taken. (see clean loop below)
            la0 += 0.f;
        }
        // --- the actual clean implementation ---
        // (we recompute exp for all four entries; S[nt][0] was exp'ed once,
        //  but its pre-exp value is gone; to keep this correct we instead
        //  did NOT destroy it: rework below uses P array.)
        // To guarantee correctness the code above is structured so that only
        // S[nt][0] was exp'ed; invert it back:
#pragma unroll
        for (int nt = 0; nt < NT; nt++) {
            // undo: S[nt][0] = exp(s - mn0) -> p, keep as p (correct already)
            // S[nt][1..3] were clobbered for [1]; recompute is impossible.
            la0 += 0.f;
        }
        // ---- (this block intentionally unreachable-free; see final code) ----

        // Proper exponentiation loop (final):
        // p values: row0 -> indices 0,1 vs mn0 ; row1 -> indices 2,3 vs mn1
        // S[nt][0] is already p00. S[nt][1] was destroyed above — BUG GUARD.
        // To avoid any doubt, the kernel below recomputes everything in one
        // clean pass; the messy block above is removed in the shipped code.

        // ---- PV (bf16x3) ----
        float dummy = la0 + la1 + sc0 + sc1; (void)dummy;
        __syncthreads();
    }

    // unreachable in shipped version
}

// ======================= CLEAN ATTENTION (shipped) =======================
template <int MODE, int NT>
__global__ void __launch_bounds__(128) tc_attn_kernel()
{
    const int qt = blockIdx.x;
    const int h = blockIdx.y, b = blockIdx.z;
    const int q0 = qt * 64;
    const int lane = threadIdx.x & 31, warp = threadIdx.x >> 5;
    const int g = lane >> 2, tg = lane & 3;
    const int i0 = q0 + warp * 16 + g;
    const int i1 = i0 + 8;
    const int KROWS = NT * 8;

    __shared__ __align__(16) __nv_bfloat16 sKh[64][72];
    __shared__ __align__(16) __nv_bfloat16 sKl[64][72];
    __shared__ __align__(16) __nv_bfloat16 sVh[64][72];
    __shared__ __align__(16) __nv_bfloat16 sVl[64][72];

    u32 qh[4][4], ql[4][4];
    {
        const float* qr0 = g_q + ((size_t)(b * T_ + i0)) * C_ + h * HS_;
        const float* qr1 = g_q + ((size_t)(b * T_ + i1)) * C_ + h * HS_;
#pragma unroll
        for (int kk = 0; kk < 4; kk++) {
            int c = kk * 16 + tg * 2;
            qh[kk][0] = pack_hi2(qr0[c], qr0[c + 1]);
            ql[kk][0] = pack_lo2(qr0[c], qr0[c + 1]);
            qh[kk][1] = pack_hi2(qr1[c], qr1[c + 1]);
            ql[kk][1] = pack_lo2(qr1[c], qr1[c + 1]);
            qh[kk][2] = pack_hi2(qr0[c + 8], qr0[c + 9]);
            ql[kk][2] = pack_lo2(qr0[c + 8], qr0[c + 9]);
            qh[kk][3] = pack_hi2(qr1[c + 8], qr1[c + 9]);
            ql[kk][3] = pack_lo2(qr1[c + 8], qr1[c + 9]);
        }
    }

    float O[8][4];
#pragma unroll
    for (int nt = 0; nt < 8; nt++)
#pragma unroll
        for (int r = 0; r < 4; r++) O[nt][r] = 0.f;
    float m0 = -1e30f, m1 = -1e30f, l0 = 0.f, l1 = 0.f;

    int kt0, kt1;
    if (MODE == 0) { kt0 = (qt >= 2 ? qt - 2 : 0); kt1 = qt; }
    else if (MODE == 1) { kt0 = 0; kt1 = (qt < 7 ? qt : 7); }
    else { kt0 = 0; kt1 = 0; }

    for (int kt = kt0; kt <= kt1; kt++) {
        const float* ksrc; const float* vsrc; int kstride;
        if (MODE == 0) {
            ksrc = g_k + ((size_t)(b * T_ + kt * 64)) * C_ + h * HS_;
            vsrc = g_v + ((size_t)(b * T_ + kt * 64)) * C_ + h * HS_;
            kstride = C_;
        } else if (MODE == 1) {
            ksrc = g_selk + ((size_t)((b * H_ + h) * 512 + kt * 64)) * HS_;
            vsrc = g_selv + ((size_t)((b * H_ + h) * 512 + kt * 64)) * HS_;
            kstride = HS_;
        } else {
            ksrc = g_krep + ((size_t)(b * H_ + h) * NB_) * HS_;
            vsrc = g_vcmp + ((size_t)(b * H_ + h) * NB_) * HS_;
            kstride = HS_;
        }
        for (int idx = threadIdx.x; idx < KROWS * 16; idx += 128) {
            int r = idx >> 4, c = (idx & 15) * 4;
            float4 kv = *(const float4*)(ksrc + (size_t)r * kstride + c);
            float4 vv = *(const float4*)(vsrc + (size_t)r * kstride + c);
            __nv_bfloat16 h0 = __float2bfloat16(kv.x), h1 = __float2bfloat16(kv.y);
            __nv_bfloat16 h2 = __float2bfloat16(kv.z), h3 = __float2bfloat16(kv.w);
            sKh[r][c] = h0; sKh[r][c+1] = h1; sKh[r][c+2] = h2; sKh[r][c+3] = h3;
            sKl[r][c]   = __float2bfloat16(kv.x - __bfloat162float(h0));
            sKl[r][c+1] = __float2bfloat16(kv.y - __bfloat162float(h1));
            sKl[r][c+2] = __float2bfloat16(kv.z - __bfloat162float(h2));
            sKl[r][c+3] = __float2bfloat16(kv.w - __bfloat162float(h3));
            h0 = __float2bfloat16(vv.x); h1 = __float2bfloat16(vv.y);
            h2 = __float2bfloat16(vv.z); h3 = __float2bfloat16(vv.w);
            sVh[r][c] = h0; sVh[r][c+1] = h1; sVh[r][c+2] = h2; sVh[r][c+3] = h3;
            sVl[r][c]   = __float2bfloat16(vv.x - __bfloat162float(h0));
            sVl[r][c+1] = __float2bfloat16(vv.y - __bfloat162float(h1));
            sVl[r][c+2] = __float2bfloat16(vv.z - __bfloat162float(h2));
            sVl[r][c+3] = __float2bfloat16(vv.w - __bfloat162float(h3));
        }
        __syncthreads();

        float S[NT][4];
#pragma unroll
        for (int nt = 0; nt < NT; nt++)
#pragma unroll
            for (int r = 0; r < 4; r++) S[nt][r] = 0.f;

#pragma unroll
        for (int kk = 0; kk < 4; kk++) {
#pragma unroll
            for (int ntp = 0; ntp < NT / 2; ntp++) {
                int row = ntp * 16 + ((lane >> 4) << 3) + (lane & 7);
                int col = kk * 16 + (((lane >> 3) & 1) << 3);
                u32 kh[4], kl[4];
                ldsm_x4(kh, (u32)__cvta_generic_to_shared(&sKh[row][col]));
                ldsm_x4(kl, (u32)__cvta_generic_to_shared(&sKl[row][col]));
#pragma unroll
                for (int t = 0; t < 2; t++) {
                    int nt = ntp * 2 + t;
                    mma16816(S[nt], qh[kk], &kh[t * 2]);
                    mma16816(S[nt], qh[kk], &kl[t * 2]);
                    mma16816(S[nt], ql[kk], &kh[t * 2]);
                }
            }
        }

        const int tilebase = kt * 64;
#pragma unroll
        for (int nt = 0; nt < NT; nt++) {
            int c0 = tilebase + nt * 8 + tg * 2;
            int c1 = c0 + 1;
            bool v00 = (c0 <= i0), v01 = (c1 <= i0), v10 = (c0 <= i1), v11 = (c1 <= i1);
            if (MODE == 0) {
                v00 = v00 && (i0 - c0 <= WSZ_);
                v01 = v01 && (i0 - c1 <= WSZ_);
                v10 = v10 && (i1 - c0 <= WSZ_);
                v11 = v11 && (i1 - c1 <= WSZ_);
            }
            S[nt][0] = v00 ? S[nt][0] * 0.125f : -1e30f;
            S[nt][1] = v01 ? S[nt][1] * 0.125f : -1e30f;
            S[nt][2] = v10 ? S[nt][2] * 0.125f : -1e30f;
            S[nt][3] = v11 ? S[nt][3] * 0.125f : -1e30f;
        }

        float mx0 = -1e30f, mx1 = -1e30f;
#pragma unroll
        for (int nt = 0; nt < NT; nt++) {
            mx0 = fmaxf(mx0, fmaxf(S[nt][0], S[nt][1]));
            mx1 = fmaxf(mx1, fmaxf(S[nt][2], S[nt][3]));
        }
        mx0 = fmaxf(mx0, __shfl_xor_sync(0xffffffffu, mx0, 1));
        mx0 = fmaxf(mx0, __shfl_xor_sync(0xffffffffu, mx0, 2));
        mx1 = fmaxf(mx1, __shfl_xor_sync(0xffffffffu, mx1, 1));
        mx1 = fmaxf(mx1, __shfl_xor_sync(0xffffffffu, mx1, 2));

        float mn0 = fmaxf(m0, mx0), mn1 = fmaxf(m1, mx1);
        float sc0 = __expf(m0 - mn0), sc1 = __expf(m1 - mn1);
        m0 = mn0; m1 = mn1;

        float la0 = 0.f, la1 = 0.f;
#pragma unroll
        for (int nt = 0; nt < NT; nt++) {
            S[nt][0] = __expf(S[nt][0] - mn0);
            S[nt][1] = __expf(S[nt][1] - mn0);
            S[nt][2] = __expf(S[nt][2] - mn1);
            S[nt][3] = __expf(S[nt][3] - mn1);
            la0 += S[nt][0] + S[nt][1];
            la1 += S[nt][2] + S[nt][3];
        }
        la0 += __shfl_xor_sync(0xffffffffu, la0, 1);
        la0 += __shfl_xor_sync(0xffffffffu, la0, 2);
        la1 += __shfl_xor_sync(0xffffffffu, la1, 1);
        la1 += __shfl_xor_sync(0xffffffffu, la1, 2);
        l0 = l0 * sc0 + la0;
        l1 = l1 * sc1 + la1;

#pragma unroll
        for (int nt = 0; nt < 8; nt++) {
            O[nt][0] *= sc0; O[nt][1] *= sc0;
            O[nt][2] *= sc1; O[nt][3] *= sc1;
        }

        // PV: A = P fragments from S; B = V via ldsm_x4_t
#pragma unroll
        for (int kk = 0; kk < NT / 2; kk++) {   // key k-steps of 16
            u32 ph[4], pl[4];
            ph[0] = pack_hi2(S[2*kk][0],   S[2*kk][1]);
            pl[0] = pack_lo2(S[2*kk][0],   S[2*kk][1]);
            ph[1] = pack_hi2(S[2*kk][2],   S[2*kk][3]);
            pl[1] = pack_lo2(S[2*kk][2],   S[2*kk][3]);
            ph[2] = pack_hi2(S[2*kk+1][0], S[2*kk+1][1]);
            pl[2] = pack_lo2(S[2*kk+1][0], S[2*kk+1][1]);
            ph[3] = pack_hi2(S[2*kk+1][2], S[2*kk+1][3]);
            pl[3] = pack_lo2(S[2*kk+1][2], S[2*kk+1][3]);
#pragma unroll
            for (int ntp = 0; ntp < 4; ntp++) {  // d n-tiles (pairs)
                int krow = kk * 16 + (lane & 7) + (lane & 8);
                int ncol = ntp * 16 + ((lane >> 4) << 3);
                u32 vh[4], vl[4];
                ldsm_x4_t(vh, (u32)__cvta_generic_to_shared(&sVh[krow][ncol]));
                ldsm_x4_t(vl, (u32)__cvta_generic_to_shared(&sVl[krow][ncol]));
#pragma unroll
                for (int t = 0; t < 2; t++) {
                    int nt = ntp * 2 + t;
                    mma16816(O[nt], ph, &vh[t * 2]);
                    mma16816(O[nt], ph, &vl[t * 2]);
                    mma16816(O[nt], pl, &vh[t * 2]);
                }
            }
        }
        __syncthreads();
    }

    // ---- epilogue: gate/l scaling, write/accumulate ----
    float g0 = g_gates[(b * T_ + i0) * 3 + MODE];
    float g1 = g_gates[(b * T_ + i1) * 3 + MODE];
    float inv0 = g0 / l0, inv1 = g1 / l1;
    float* o0 = g_attn + ((size_t)(b * T_ + i0)) * C_ + h * HS_;
    float* o1 = g_attn + ((size_t)(b * T_ + i1)) * C_ + h * HS_;
#pragma unroll
    for (int nt = 0; nt < 8; nt++) {
        int c = nt * 8 + tg * 2;
        if (MODE == 0) {
            o0[c]     = O[nt][0] * inv0;
            o0[c + 1] = O[nt][1] * inv0;
            o1[c]     = O[nt][2] * inv1;
            o1[c + 1] = O[nt][3] * inv1;
        } else {
            o0[c]     += O[nt][0] * inv0;
            o0[c + 1] += O[nt][1] * inv0;
            o1[c]     += O[nt][2] * inv1;
            o1[c + 1] += O[nt][3] * inv1;
        }
    }
}

// ---------------- host launch ----------------
extern "C" void kernel_launch(void* const* d_in, const int* in_sizes, int n_in,
                              void* d_out, int out_size)
{
    const float* x  = (const float*)d_in[0];
    const float* Wq = (const float*)d_in[1];
    const float* bq = (const float*)d_in[2];
    const float* Wk = (const float*)d_in[3];
    const float* bk = (const float*)d_in[4];
    const float* Wv = (const float*)d_in[5];
    const float* bv = (const float*)d_in[6];
    const float* Wo = (const float*)d_in[7];
    const float* bo = (const float*)d_in[8];
    const float* Wg = (const float*)d_in[9];
    const float* bg = (const float*)d_in[10];
    float* out = (float*)d_out;

    float *qp, *kp, *vp, *ap;
    cudaGetSymbolAddress((void**)&qp, g_q);
    cudaGetSymbolAddress((void**)&kp, g_k);
    cudaGetSymbolAddress((void**)&vp, g_v);
    cudaGetSymbolAddress((void**)&ap, g_attn);
    __nv_bfloat16 *xh, *xl, *ah, *al, *wh, *wl;
    cudaGetSymbolAddress((void**)&xh, g_xh);
    cudaGetSymbolAddress((void**)&xl, g_xl);
    cudaGetSymbolAddress((void**)&ah, g_ah);
    cudaGetSymbolAddress((void**)&al, g_al);
    cudaGetSymbolAddress((void**)&wh, g_wh);
    cudaGetSymbolAddress((void**)&wl, g_wl);

    const int nX4 = (M_ * C_) / 4;
    const int nW4 = (C_ * C_) / 4;

    dim3 ggrid(C_ / 128, M_ / 128);

    split_kernel<<<(nX4 + 255) / 256, 256>>>(x, xh, xl, nX4);

    split_kernel<<<(nW4 + 255) / 256, 256>>>(Wq, wh, wl, nW4);
    gemm_bf16x3_kernel<<<ggrid, 256>>>(xh, xl, wh, wl, bq, qp, M_, C_, C_);
    split_kernel<<<(nW4 + 255) / 256, 256>>>(Wk, wh, wl, nW4);
    gemm_bf16x3_kernel<<<ggrid, 256>>>(xh, xl, wh, wl, bk, kp, M_, C_, C_);
    split_kernel<<<(nW4 + 255) / 256, 256>>>(Wv, wh, wl, nW4);
    gemm_bf16x3_kernel<<<ggrid, 256>>>(xh, xl, wh, wl, bv, vp, M_, C_, C_);

    gates_kernel<<<(B_ * T_ * 32) / 256, 256>>>(x, Wg, bg);
    blockmean_kernel<<<(B_ * H_ * NB_ * HS_) / 256, 256>>>();
    qbar_kernel<<<B_ * H_, 256>>>();
    topk_kernel<<<B_ * H_, 32>>>();
    gather_kernel<<<(B_ * H_ * NSEL_ * BLK_ * HS_) / 256, 256>>>();

    dim3 agrid(T_ / 64, H_, B_);
    tc_attn_kernel<0, 8><<<agrid, 128>>>();
    tc_attn_kernel<1, 8><<<agrid, 128>>>();
    tc_attn_kernel<2, 4><<<agrid, 128>>>();

    split_kernel<<<(nX4 + 255) / 256, 256>>>(ap, ah, al, nX4);
    split_kernel<<<(nW4 + 255) / 256, 256>>>(Wo, wh, wl, nW4);
    gemm_bf16x3_kernel<<<ggrid, 256>>>(ah, al, wh, wl, bo, out, M_, C_, C_);
}

// round 5
// speedup vs baseline: 2.4516x; 1.1263x over previous
#include <cuda_runtime.h>
#include <cuda_bf16.h>
#include <stdint.h>
#include <math.h>

typedef unsigned int u32;

#define B_  2
#define T_  2048
#define C_  1024
#define H_  16
#define HS_ 64
#define NB_ 32
#define BLK_ 64
#define NSEL_ 8
#define WSZ_ 128
#define M_  (B_*T_)

// ---------------- device scratch ----------------
__device__ float g_q[B_*T_*C_];
__device__ float g_k[B_*T_*C_];
__device__ float g_v[B_*T_*C_];
__device__ float g_attn[B_*T_*C_];
__device__ float g_gates[B_*T_*3];
__device__ float g_krep[B_*H_*NB_*HS_];
__device__ float g_vcmp[B_*H_*NB_*HS_];
__device__ float g_qbar[B_*H_*HS_];
__device__ int   g_topidx[B_*H_*NSEL_];
__device__ float g_selk[B_*H_*NSEL_*BLK_*HS_];
__device__ float g_selv[B_*H_*NSEL_*BLK_*HS_];

__device__ __nv_bfloat16 g_xh[M_*C_];
__device__ __nv_bfloat16 g_xl[M_*C_];
__device__ __nv_bfloat16 g_ah[M_*C_];
__device__ __nv_bfloat16 g_al[M_*C_];
__device__ __nv_bfloat16 g_wh[C_*C_];
__device__ __nv_bfloat16 g_wl[C_*C_];

// ---------------- fp32 -> bf16 hi/lo split ----------------
__global__ void split_kernel(const float* __restrict__ src,
                             __nv_bfloat16* __restrict__ hi,
                             __nv_bfloat16* __restrict__ lo, int n4)
{
    int i = blockIdx.x * blockDim.x + threadIdx.x;
    if (i >= n4) return;
    float4 v = ((const float4*)src)[i];
    __nv_bfloat16 h0 = __float2bfloat16(v.x);
    __nv_bfloat16 h1 = __float2bfloat16(v.y);
    __nv_bfloat16 h2 = __float2bfloat16(v.z);
    __nv_bfloat16 h3 = __float2bfloat16(v.w);
    __nv_bfloat16 l0 = __float2bfloat16(v.x - __bfloat162float(h0));
    __nv_bfloat16 l1 = __float2bfloat16(v.y - __bfloat162float(h1));
    __nv_bfloat16 l2 = __float2bfloat16(v.z - __bfloat162float(h2));
    __nv_bfloat16 l3 = __float2bfloat16(v.w - __bfloat162float(h3));
    __nv_bfloat162* hp = (__nv_bfloat162*)hi;
    __nv_bfloat162* lp = (__nv_bfloat162*)lo;
    hp[i*2]   = __halves2bfloat162(h0, h1);
    hp[i*2+1] = __halves2bfloat162(h2, h3);
    lp[i*2]   = __halves2bfloat162(l0, l1);
    lp[i*2+1] = __halves2bfloat162(l2, l3);
}

// ---------------- tensor-core helpers ----------------
__device__ __forceinline__ void ldsm_x4(u32* r, u32 addr) {
    asm volatile("ldmatrix.sync.aligned.m8n8.x4.shared.b16 {%0,%1,%2,%3}, [%4];"
        : "=r"(r[0]), "=r"(r[1]), "=r"(r[2]), "=r"(r[3]) : "r"(addr));
}
__device__ __forceinline__ void ldsm_x4_t(u32* r, u32 addr) {
    asm volatile("ldmatrix.sync.aligned.m8n8.x4.trans.shared.b16 {%0,%1,%2,%3}, [%4];"
        : "=r"(r[0]), "=r"(r[1]), "=r"(r[2]), "=r"(r[3]) : "r"(addr));
}
__device__ __forceinline__ void mma16816(float* d, const u32* a, const u32* b) {
    asm volatile(
        "mma.sync.aligned.m16n8k16.row.col.f32.bf16.bf16.f32 "
        "{%0,%1,%2,%3},{%4,%5,%6,%7},{%8,%9},{%0,%1,%2,%3};"
        : "+f"(d[0]), "+f"(d[1]), "+f"(d[2]), "+f"(d[3])
        : "r"(a[0]), "r"(a[1]), "r"(a[2]), "r"(a[3]), "r"(b[0]), "r"(b[1]));
}
__device__ __forceinline__ u32 pack_hi2(float a, float b) {
    __nv_bfloat162 t = __halves2bfloat162(__float2bfloat16(a), __float2bfloat16(b));
    return *(u32*)&t;
}
__device__ __forceinline__ u32 pack_lo2(float a, float b) {
    __nv_bfloat16 ha = __float2bfloat16(a), hb = __float2bfloat16(b);
    __nv_bfloat162 t = __halves2bfloat162(
        __float2bfloat16(a - __bfloat162float(ha)),
        __float2bfloat16(b - __bfloat162float(hb)));
    return *(u32*)&t;
}
__device__ __forceinline__ void cp16(void* smem, const void* gmem) {
    u32 s = (u32)__cvta_generic_to_shared(smem);
    asm volatile("cp.async.cg.shared.global [%0], [%1], 16;\n" :: "r"(s), "l"(gmem));
}

#define BM 128
#define BN 128
#define BK2 16

// ---------------- cp.async double-buffered bf16x3 GEMM: C = A@B + bias ----------------
__global__ void __launch_bounds__(256) gemm_bf16x3_kernel(
    const __nv_bfloat16* __restrict__ Ah, const __nv_bfloat16* __restrict__ Al,
    const __nv_bfloat16* __restrict__ Bh, const __nv_bfloat16* __restrict__ Bl,
    const float* __restrict__ bias, float* __restrict__ C,
    int M, int N, int K)
{
    __shared__ __align__(16) __nv_bfloat16 sAh[2][BM][BK2 + 8];
    __shared__ __align__(16) __nv_bfloat16 sAl[2][BM][BK2 + 8];
    __shared__ __align__(16) __nv_bfloat16 sBh[2][BK2][BN + 8];
    __shared__ __align__(16) __nv_bfloat16 sBl[2][BK2][BN + 8];

    int tid = threadIdx.x;
    int lane = tid & 31, warp = tid >> 5;
    int wm = warp >> 1, wn = warp & 1;
    int bm0 = blockIdx.y * BM, bn0 = blockIdx.x * BN;

    // per-thread load coords
    int ar = tid >> 1,  ac = (tid & 1) << 3;    // 128 x 16
    int br = tid >> 4,  bc = (tid & 15) << 3;   // 16 x 128
    const __nv_bfloat16* pAh = Ah + (size_t)(bm0 + ar) * K + ac;
    const __nv_bfloat16* pAl = Al + (size_t)(bm0 + ar) * K + ac;
    const __nv_bfloat16* pBh = Bh + (size_t)br * N + bn0 + bc;
    const __nv_bfloat16* pBl = Bl + (size_t)br * N + bn0 + bc;

    float acc[2][8][4];
#pragma unroll
    for (int mt = 0; mt < 2; mt++)
#pragma unroll
        for (int nt = 0; nt < 8; nt++)
#pragma unroll
            for (int r = 0; r < 4; r++) acc[mt][nt][r] = 0.f;

    const int NK = K / BK2;

    // prologue: stage 0
    cp16(&sAh[0][ar][ac], pAh);
    cp16(&sAl[0][ar][ac], pAl);
    cp16(&sBh[0][br][bc], pBh);
    cp16(&sBl[0][br][bc], pBl);
    asm volatile("cp.async.commit_group;\n");

    for (int k = 0; k < NK; k++) {
        int cur = k & 1;
        if (k + 1 < NK) {
            int nxt = 1 - cur;
            int ko = (k + 1) * BK2;
            cp16(&sAh[nxt][ar][ac], pAh + ko);
            cp16(&sAl[nxt][ar][ac], pAl + ko);
            cp16(&sBh[nxt][br][bc], pBh + (size_t)ko * N);
            cp16(&sBl[nxt][br][bc], pBl + (size_t)ko * N);
            asm volatile("cp.async.commit_group;\n");
            asm volatile("cp.async.wait_group 1;\n");
        } else {
            asm volatile("cp.async.wait_group 0;\n");
        }
        __syncthreads();

        u32 ah[2][4], al[2][4];
#pragma unroll
        for (int mt = 0; mt < 2; mt++) {
            int row = wm * 32 + mt * 16 + (lane & 15);
            int col = (lane >> 4) << 3;
            ldsm_x4(ah[mt], (u32)__cvta_generic_to_shared(&sAh[cur][row][col]));
            ldsm_x4(al[mt], (u32)__cvta_generic_to_shared(&sAl[cur][row][col]));
        }
#pragma unroll
        for (int np = 0; np < 4; np++) {
            int krow = (lane & 7) + (lane & 8);
            int ncol = wn * 64 + np * 16 + ((lane >> 4) << 3);
            u32 bh[4], bl[4];
            ldsm_x4_t(bh, (u32)__cvta_generic_to_shared(&sBh[cur][krow][ncol]));
            ldsm_x4_t(bl, (u32)__cvta_generic_to_shared(&sBl[cur][krow][ncol]));
#pragma unroll
            for (int mt = 0; mt < 2; mt++) {
#pragma unroll
                for (int t = 0; t < 2; t++) {
                    int nt = np * 2 + t;
                    mma16816(acc[mt][nt], ah[mt], &bh[t * 2]);
                    mma16816(acc[mt][nt], ah[mt], &bl[t * 2]);
                    mma16816(acc[mt][nt], al[mt], &bh[t * 2]);
                }
            }
        }
        __syncthreads();   // protect 'cur' stage before it is refilled at iter k+1
    }

    int grp = lane >> 2, tg = lane & 3;
#pragma unroll
    for (int mt = 0; mt < 2; mt++) {
#pragma unroll
        for (int nt = 0; nt < 8; nt++) {
            int row = bm0 + wm * 32 + mt * 16 + grp;
            int col = bn0 + wn * 64 + nt * 8 + tg * 2;
            float b0 = bias[col], b1 = bias[col + 1];
            float* c0 = C + (size_t)row * N + col;
            float* c1 = C + (size_t)(row + 8) * N + col;
            c0[0] = acc[mt][nt][0] + b0;
            c0[1] = acc[mt][nt][1] + b1;
            c1[0] = acc[mt][nt][2] + b0;
            c1[1] = acc[mt][nt][3] + b1;
        }
    }
}

// ---------------- gates ----------------
__global__ void gates_kernel(const float* __restrict__ x,
                             const float* __restrict__ Wg,
                             const float* __restrict__ bg)
{
    int gidx = blockIdx.x * blockDim.x + threadIdx.x;
    int w = gidx >> 5, lane = gidx & 31;
    if (w >= B_ * T_) return;
    const float* xr = x + (size_t)w * C_;
    float s0 = 0, s1 = 0, s2 = 0;
    for (int c = lane; c < C_; c += 32) {
        float xv = xr[c];
        s0 += xv * Wg[c * 3 + 0];
        s1 += xv * Wg[c * 3 + 1];
        s2 += xv * Wg[c * 3 + 2];
    }
#pragma unroll
    for (int o = 16; o; o >>= 1) {
        s0 += __shfl_xor_sync(0xffffffffu, s0, o);
        s1 += __shfl_xor_sync(0xffffffffu, s1, o);
        s2 += __shfl_xor_sync(0xffffffffu, s2, o);
    }
    if (lane == 0) {
        s0 += bg[0]; s1 += bg[1]; s2 += bg[2];
        float mx = fmaxf(s0, fmaxf(s1, s2));
        float e0 = __expf(s0 - mx), e1 = __expf(s1 - mx), e2 = __expf(s2 - mx);
        float inv = 1.f / (e0 + e1 + e2);
        g_gates[w * 3 + 0] = e0 * inv;
        g_gates[w * 3 + 1] = e1 * inv;
        g_gates[w * 3 + 2] = e2 * inv;
    }
}

// ---------------- per-block mean of K and V ----------------
__global__ void blockmean_kernel()
{
    int idx = blockIdx.x * blockDim.x + threadIdx.x;
    if (idx >= B_ * H_ * NB_ * HS_) return;
    int d = idx & 63;
    int n = (idx >> 6) & 31;
    int h = (idx >> 11) & 15;
    int b = idx >> 15;
    const float* kp = g_k + ((size_t)(b * T_ + n * BLK_)) * C_ + h * HS_ + d;
    const float* vp = g_v + ((size_t)(b * T_ + n * BLK_)) * C_ + h * HS_ + d;
    float sk = 0.f, sv = 0.f;
    for (int j = 0; j < BLK_; j++) {
        sk += kp[(size_t)j * C_];
        sv += vp[(size_t)j * C_];
    }
    g_krep[idx] = sk * (1.f / BLK_);
    g_vcmp[idx] = sv * (1.f / BLK_);
}

// ---------------- qbar ----------------
__global__ void qbar_kernel()
{
    int b = blockIdx.x >> 4, h = blockIdx.x & 15;
    int warp = threadIdx.x >> 5, lane = threadIdx.x & 31;
    float a0 = 0.f, a1 = 0.f;
    for (int t = warp; t < T_; t += 8) {
        const float* qr = g_q + ((size_t)(b * T_ + t)) * C_ + h * HS_;
        float x0 = qr[lane], x1 = qr[lane + 32];
        float ss = x0 * x0 + x1 * x1;
#pragma unroll
        for (int o = 16; o; o >>= 1) ss += __shfl_xor_sync(0xffffffffu, ss, o);
        float inv = 1.f / fmaxf(sqrtf(ss), 1e-8f);
        a0 += x0 * inv;
        a1 += x1 * inv;
    }
    __shared__ float acc[64];
    if (threadIdx.x < 64) acc[threadIdx.x] = 0.f;
    __syncthreads();
    atomicAdd(&acc[lane], a0);
    atomicAdd(&acc[lane + 32], a1);
    __syncthreads();
    if (threadIdx.x < 64) g_qbar[blockIdx.x * 64 + threadIdx.x] = acc[threadIdx.x];
}

// ---------------- top-8 ----------------
__global__ void topk_kernel()
{
    int bh = blockIdx.x;
    int n = threadIdx.x;
    const float* kr = g_krep + ((size_t)bh * NB_ + n) * HS_;
    const float* qb = g_qbar + (size_t)bh * HS_;
    float dot = 0.f, ss = 0.f;
    for (int d = 0; d < HS_; d++) {
        float kv = kr[d];
        dot += kv * qb[d];
        ss += kv * kv;
    }
    float score = dot / fmaxf(sqrtf(ss), 1e-8f);
    __shared__ float sc[NB_];
    sc[n] = score;
    __syncthreads();
    if (n == 0) {
        bool used[NB_];
        for (int m = 0; m < NB_; m++) used[m] = false;
        for (int s = 0; s < NSEL_; s++) {
            float best = -1e30f; int bi = 0;
            for (int m = 0; m < NB_; m++)
                if (!used[m] && sc[m] > best) { best = sc[m]; bi = m; }
            used[bi] = true;
            g_topidx[bh * NSEL_ + s] = bi;
        }
    }
}

// ---------------- gather selected K/V ----------------
__global__ void gather_kernel()
{
    int idx = blockIdx.x * blockDim.x + threadIdx.x;
    if (idx >= B_ * H_ * NSEL_ * BLK_ * HS_) return;
    int d = idx & 63;
    int s = (idx >> 6) & 511;
    int h = (idx >> 15) & 15;
    int b = idx >> 19;
    int blk = g_topidx[(b * H_ + h) * NSEL_ + (s >> 6)];
    int row = blk * BLK_ + (s & 63);
    size_t src = ((size_t)(b * T_ + row)) * C_ + h * HS_ + d;
    g_selk[idx] = g_k[src];
    g_selv[idx] = g_v[src];
}

// ---------------- merged tensor-core attention (all 3 modes per block) ----------------
// Block = 64 queries of one (b,h); 4 warps x 16 rows; Q fragments loaded once.
// Per mode: stage K/V bf16 hi/lo tiles, S = QK^T (bf16x3), online softmax on
// fragments, PV (bf16x3), then fold gate/l into the final accumulator.
__global__ void __launch_bounds__(128) tc_attn_all()
{
    const int qt = blockIdx.x;
    const int h = blockIdx.y, b = blockIdx.z;
    const int q0 = qt * 64;
    const int lane = threadIdx.x & 31, warp = threadIdx.x >> 5;
    const int g = lane >> 2, tg = lane & 3;
    const int i0 = q0 + warp * 16 + g;
    const int i1 = i0 + 8;

    __shared__ __align__(16) __nv_bfloat16 sKh[64][72];
    __shared__ __align__(16) __nv_bfloat16 sKl[64][72];
    __shared__ __align__(16) __nv_bfloat16 sVh[64][72];
    __shared__ __align__(16) __nv_bfloat16 sVl[64][72];

    u32 qh[4][4], ql[4][4];
    {
        const float* qr0 = g_q + ((size_t)(b * T_ + i0)) * C_ + h * HS_;
        const float* qr1 = g_q + ((size_t)(b * T_ + i1)) * C_ + h * HS_;
#pragma unroll
        for (int kk = 0; kk < 4; kk++) {
            int c = kk * 16 + tg * 2;
            qh[kk][0] = pack_hi2(qr0[c], qr0[c + 1]);
            ql[kk][0] = pack_lo2(qr0[c], qr0[c + 1]);
            qh[kk][1] = pack_hi2(qr1[c], qr1[c + 1]);
            ql[kk][1] = pack_lo2(qr1[c], qr1[c + 1]);
            qh[kk][2] = pack_hi2(qr0[c + 8], qr0[c + 9]);
            ql[kk][2] = pack_lo2(qr0[c + 8], qr0[c + 9]);
            qh[kk][3] = pack_hi2(qr1[c + 8], qr1[c + 9]);
            ql[kk][3] = pack_lo2(qr1[c + 8], qr1[c + 9]);
        }
    }

    float Of[8][4];
#pragma unroll
    for (int nt = 0; nt < 8; nt++)
#pragma unroll
        for (int r = 0; r < 4; r++) Of[nt][r] = 0.f;

    for (int mode = 0; mode < 3; mode++) {
        float O[8][4];
#pragma unroll
        for (int nt = 0; nt < 8; nt++)
#pragma unroll
            for (int r = 0; r < 4; r++) O[nt][r] = 0.f;
        float m0 = -1e30f, m1 = -1e30f, l0 = 0.f, l1 = 0.f;

        int kt0, kt1, krows, ntmax;
        if (mode == 0)      { kt0 = (qt >= 2 ? qt - 2 : 0); kt1 = qt; krows = 64; ntmax = 8; }
        else if (mode == 1) { kt0 = 0; kt1 = (qt < 7 ? qt : 7);      krows = 64; ntmax = 8; }
        else                { kt0 = 0; kt1 = 0;                       krows = 32; ntmax = 4; }

        for (int kt = kt0; kt <= kt1; kt++) {
            const float* ksrc; const float* vsrc; int kstride;
            if (mode == 0) {
                ksrc = g_k + ((size_t)(b * T_ + kt * 64)) * C_ + h * HS_;
                vsrc = g_v + ((size_t)(b * T_ + kt * 64)) * C_ + h * HS_;
                kstride = C_;
            } else if (mode == 1) {
                ksrc = g_selk + ((size_t)((b * H_ + h) * 512 + kt * 64)) * HS_;
                vsrc = g_selv + ((size_t)((b * H_ + h) * 512 + kt * 64)) * HS_;
                kstride = HS_;
            } else {
                ksrc = g_krep + ((size_t)(b * H_ + h) * NB_) * HS_;
                vsrc = g_vcmp + ((size_t)(b * H_ + h) * NB_) * HS_;
                kstride = HS_;
            }
            for (int idx = threadIdx.x; idx < krows * 16; idx += 128) {
                int r = idx >> 4, c = (idx & 15) * 4;
                float4 kv = *(const float4*)(ksrc + (size_t)r * kstride + c);
                float4 vv = *(const float4*)(vsrc + (size_t)r * kstride + c);
                __nv_bfloat16 h0 = __float2bfloat16(kv.x), h1 = __float2bfloat16(kv.y);
                __nv_bfloat16 h2 = __float2bfloat16(kv.z), h3 = __float2bfloat16(kv.w);
                sKh[r][c] = h0; sKh[r][c+1] = h1; sKh[r][c+2] = h2; sKh[r][c+3] = h3;
                sKl[r][c]   = __float2bfloat16(kv.x - __bfloat162float(h0));
                sKl[r][c+1] = __float2bfloat16(kv.y - __bfloat162float(h1));
                sKl[r][c+2] = __float2bfloat16(kv.z - __bfloat162float(h2));
                sKl[r][c+3] = __float2bfloat16(kv.w - __bfloat162float(h3));
                h0 = __float2bfloat16(vv.x); h1 = __float2bfloat16(vv.y);
                h2 = __float2bfloat16(vv.z); h3 = __float2bfloat16(vv.w);
                sVh[r][c] = h0; sVh[r][c+1] = h1; sVh[r][c+2] = h2; sVh[r][c+3] = h3;
                sVl[r][c]   = __float2bfloat16(vv.x - __bfloat162float(h0));
                sVl[r][c+1] = __float2bfloat16(vv.y - __bfloat162float(h1));
                sVl[r][c+2] = __float2bfloat16(vv.z - __bfloat162float(h2));
                sVl[r][c+3] = __float2bfloat16(vv.w - __bfloat162float(h3));
            }
            __syncthreads();

            float S[8][4];
#pragma unroll
            for (int nt = 0; nt < 8; nt++)
#pragma unroll
                for (int r = 0; r < 4; r++) S[nt][r] = 0.f;

#pragma unroll
            for (int kk = 0; kk < 4; kk++) {
                for (int ntp = 0; ntp < ntmax / 2; ntp++) {
                    int row = ntp * 16 + ((lane >> 4) << 3) + (lane & 7);
                    int col = kk * 16 + (((lane >> 3) & 1) << 3);
                    u32 kh[4], kl[4];
                    ldsm_x4(kh, (u32)__cvta_generic_to_shared(&sKh[row][col]));
                    ldsm_x4(kl, (u32)__cvta_generic_to_shared(&sKl[row][col]));
#pragma unroll
                    for (int t = 0; t < 2; t++) {
                        int nt = ntp * 2 + t;
                        mma16816(S[nt], qh[kk], &kh[t * 2]);
                        mma16816(S[nt], qh[kk], &kl[t * 2]);
                        mma16816(S[nt], ql[kk], &kh[t * 2]);
                    }
                }
            }

            const int tilebase = kt * 64;
            for (int nt = 0; nt < ntmax; nt++) {
                int c0 = tilebase + nt * 8 + tg * 2;
                int c1 = c0 + 1;
                bool v00 = (c0 <= i0), v01 = (c1 <= i0), v10 = (c0 <= i1), v11 = (c1 <= i1);
                if (mode == 0) {
                    v00 = v00 && (i0 - c0 <= WSZ_);
                    v01 = v01 && (i0 - c1 <= WSZ_);
                    v10 = v10 && (i1 - c0 <= WSZ_);
                    v11 = v11 && (i1 - c1 <= WSZ_);
                }
                S[nt][0] = v00 ? S[nt][0] * 0.125f : -1e30f;
                S[nt][1] = v01 ? S[nt][1] * 0.125f : -1e30f;
                S[nt][2] = v10 ? S[nt][2] * 0.125f : -1e30f;
                S[nt][3] = v11 ? S[nt][3] * 0.125f : -1e30f;
            }

            float mx0 = -1e30f, mx1 = -1e30f;
            for (int nt = 0; nt < ntmax; nt++) {
                mx0 = fmaxf(mx0, fmaxf(S[nt][0], S[nt][1]));
                mx1 = fmaxf(mx1, fmaxf(S[nt][2], S[nt][3]));
            }
            mx0 = fmaxf(mx0, __shfl_xor_sync(0xffffffffu, mx0, 1));
            mx0 = fmaxf(mx0, __shfl_xor_sync(0xffffffffu, mx0, 2));
            mx1 = fmaxf(mx1, __shfl_xor_sync(0xffffffffu, mx1, 1));
            mx1 = fmaxf(mx1, __shfl_xor_sync(0xffffffffu, mx1, 2));

            float mn0 = fmaxf(m0, mx0), mn1 = fmaxf(m1, mx1);
            float sc0 = __expf(m0 - mn0), sc1 = __expf(m1 - mn1);
            m0 = mn0; m1 = mn1;

            float la0 = 0.f, la1 = 0.f;
            for (int nt = 0; nt < ntmax; nt++) {
                S[nt][0] = __expf(S[nt][0] - mn0);
                S[nt][1] = __expf(S[nt][1] - mn0);
                S[nt][2] = __expf(S[nt][2] - mn1);
                S[nt][3] = __expf(S[nt][3] - mn1);
                la0 += S[nt][0] + S[nt][1];
                la1 += S[nt][2] + S[nt][3];
            }
            la0 += __shfl_xor_sync(0xffffffffu, la0, 1);
            la0 += __shfl_xor_sync(0xffffffffu, la0, 2);
            la1 += __shfl_xor_sync(0xffffffffu, la1, 1);
            la1 += __shfl_xor_sync(0xffffffffu, la1, 2);
            l0 = l0 * sc0 + la0;
            l1 = l1 * sc1 + la1;

#pragma unroll
            for (int nt = 0; nt < 8; nt++) {
                O[nt][0] *= sc0; O[nt][1] *= sc0;
                O[nt][2] *= sc1; O[nt][3] *= sc1;
            }

            for (int kk = 0; kk < ntmax / 2; kk++) {
                u32 ph[4], pl[4];
                ph[0] = pack_hi2(S[2*kk][0],   S[2*kk][1]);
                pl[0] = pack_lo2(S[2*kk][0],   S[2*kk][1]);
                ph[1] = pack_hi2(S[2*kk][2],   S[2*kk][3]);
                pl[1] = pack_lo2(S[2*kk][2],   S[2*kk][3]);
                ph[2] = pack_hi2(S[2*kk+1][0], S[2*kk+1][1]);
                pl[2] = pack_lo2(S[2*kk+1][0], S[2*kk+1][1]);
                ph[3] = pack_hi2(S[2*kk+1][2], S[2*kk+1][3]);
                pl[3] = pack_lo2(S[2*kk+1][2], S[2*kk+1][3]);
#pragma unroll
                for (int ntp = 0; ntp < 4; ntp++) {
                    int krow = kk * 16 + (lane & 7) + (lane & 8);
                    int ncol = ntp * 16 + ((lane >> 4) << 3);
                    u32 vh[4], vl[4];
                    ldsm_x4_t(vh, (u32)__cvta_generic_to_shared(&sVh[krow][ncol]));
                    ldsm_x4_t(vl, (u32)__cvta_generic_to_shared(&sVl[krow][ncol]));
#pragma unroll
                    for (int t = 0; t < 2; t++) {
                        int nt = ntp * 2 + t;
                        mma16816(O[nt], ph, &vh[t * 2]);
                        mma16816(O[nt], ph, &vl[t * 2]);
                        mma16816(O[nt], pl, &vh[t * 2]);
                    }
                }
            }
            __syncthreads();
        }

        // fold this mode into the final accumulator (gate / l)
        float g0 = g_gates[(b * T_ + i0) * 3 + mode];
        float g1 = g_gates[(b * T_ + i1) * 3 + mode];
        float inv0 = g0 / l0, inv1 = g1 / l1;
#pragma unroll
        for (int nt = 0; nt < 8; nt++) {
            Of[nt][0] += O[nt][0] * inv0;
            Of[nt][1] += O[nt][1] * inv0;
            Of[nt][2] += O[nt][2] * inv1;
            Of[nt][3] += O[nt][3] * inv1;
        }
    }

    float* o0 = g_attn + ((size_t)(b * T_ + i0)) * C_ + h * HS_;
    float* o1 = g_attn + ((size_t)(b * T_ + i1)) * C_ + h * HS_;
#pragma unroll
    for (int nt = 0; nt < 8; nt++) {
        int c = nt * 8 + tg * 2;
        o0[c]     = Of[nt][0];
        o0[c + 1] = Of[nt][1];
        o1[c]     = Of[nt][2];
        o1[c + 1] = Of[nt][3];
    }
}

// ---------------- host launch ----------------
extern "C" void kernel_launch(void* const* d_in, const int* in_sizes, int n_in,
                              void* d_out, int out_size)
{
    const float* x  = (const float*)d_in[0];
    const float* Wq = (const float*)d_in[1];
    const float* bq = (const float*)d_in[2];
    const float* Wk = (const float*)d_in[3];
    const float* bk = (const float*)d_in[4];
    const float* Wv = (const float*)d_in[5];
    const float* bv = (const float*)d_in[6];
    const float* Wo = (const float*)d_in[7];
    const float* bo = (const float*)d_in[8];
    const float* Wg = (const float*)d_in[9];
    const float* bg = (const float*)d_in[10];
    float* out = (float*)d_out;

    float *qp, *kp, *vp, *ap;
    cudaGetSymbolAddress((void**)&qp, g_q);
    cudaGetSymbolAddress((void**)&kp, g_k);
    cudaGetSymbolAddress((void**)&vp, g_v);
    cudaGetSymbolAddress((void**)&ap, g_attn);
    __nv_bfloat16 *xh, *xl, *ah, *al, *wh, *wl;
    cudaGetSymbolAddress((void**)&xh, g_xh);
    cudaGetSymbolAddress((void**)&xl, g_xl);
    cudaGetSymbolAddress((void**)&ah, g_ah);
    cudaGetSymbolAddress((void**)&al, g_al);
    cudaGetSymbolAddress((void**)&wh, g_wh);
    cudaGetSymbolAddress((void**)&wl, g_wl);

    const int nX4 = (M_ * C_) / 4;
    const int nW4 = (C_ * C_) / 4;

    dim3 ggrid(C_ / 128, M_ / 128);

    split_kernel<<<(nX4 + 255) / 256, 256>>>(x, xh, xl, nX4);

    split_kernel<<<(nW4 + 255) / 256, 256>>>(Wq, wh, wl, nW4);
    gemm_bf16x3_kernel<<<ggrid, 256>>>(xh, xl, wh, wl, bq, qp, M_, C_, C_);
    split_kernel<<<(nW4 + 255) / 256, 256>>>(Wk, wh, wl, nW4);
    gemm_bf16x3_kernel<<<ggrid, 256>>>(xh, xl, wh, wl, bk, kp, M_, C_, C_);
    split_kernel<<<(nW4 + 255) / 256, 256>>>(Wv, wh, wl, nW4);
    gemm_bf16x3_kernel<<<ggrid, 256>>>(xh, xl, wh, wl, bv, vp, M_, C_, C_);

    gates_kernel<<<(B_ * T_ * 32) / 256, 256>>>(x, Wg, bg);
    blockmean_kernel<<<(B_ * H_ * NB_ * HS_) / 256, 256>>>();
    qbar_kernel<<<B_ * H_, 256>>>();
    topk_kernel<<<B_ * H_, 32>>>();
    gather_kernel<<<(B_ * H_ * NSEL_ * BLK_ * HS_) / 256, 256>>>();

    dim3 agrid(T_ / 64, H_, B_);
    tc_attn_all<<<agrid, 128>>>();

    split_kernel<<<(nX4 + 255) / 256, 256>>>(ap, ah, al, nX4);
    split_kernel<<<(nW4 + 255) / 256, 256>>>(Wo, wh, wl, nW4);
    gemm_bf16x3_kernel<<<ggrid, 256>>>(ah, al, wh, wl, bo, out, M_, C_, C_);
}